// round 2
// baseline (speedup 1.0000x reference)
#include <cuda_runtime.h>
#include <math.h>

#define Bc   4
#define Sc   2048
#define DIN  1024
#define DOUT 1024
#define Hc   16
#define HDc  64
#define MROWS (Bc*Sc)   // 8192

// Scratch (device globals: allocation-free per harness rules)
__device__ float g_q[Bc*Hc*Sc*HDc];
__device__ float g_k[Bc*Hc*Sc*HDc];
__device__ float g_v[Bc*Hc*Sc*HDc];
__device__ float g_ctx[Bc*Sc*DOUT];

// ---------------------------------------------------------------------------
// Tiled SGEMM: C[M,N] = A[M,K] @ W[K,N] (+bias). M=8192, K=N=1024.
// 64x64 tile, BK=16, 256 threads, 4x4 microtile per thread.
// SPLIT: write output in [B,H,S,HD] layout (for q/k/v projections).
// ---------------------------------------------------------------------------
template<bool SPLIT, bool BIAS>
__global__ __launch_bounds__(256)
void gemm_kernel(const float* __restrict__ A,
                 const float* __restrict__ W,
                 const float* __restrict__ bias,
                 float* __restrict__ C) {
    constexpr int K = DIN;
    constexpr int N = DOUT;
    __shared__ float a_s[16][65];   // [k][m], transposed A tile
    __shared__ float b_s[16][65];   // [k][n]

    const int row0 = blockIdx.y * 64;
    const int col0 = blockIdx.x * 64;
    const int tid = threadIdx.x;
    const int tx = tid & 15;        // n group
    const int ty = tid >> 4;        // m group

    float acc[4][4] = {};

    for (int k0 = 0; k0 < K; k0 += 16) {
        #pragma unroll
        for (int l = 0; l < 4; l++) {
            int idx = tid + l * 256;
            int ai = idx >> 4, aj = idx & 15;      // A tile: 64 rows x 16 k
            a_s[aj][ai] = A[(row0 + ai) * K + k0 + aj];
            int bi = idx >> 6, bj = idx & 63;      // W tile: 16 k x 64 n
            b_s[bi][bj] = W[(k0 + bi) * N + col0 + bj];
        }
        __syncthreads();

        #pragma unroll
        for (int kk = 0; kk < 16; kk++) {
            float ar[4], br[4];
            #pragma unroll
            for (int r = 0; r < 4; r++) ar[r] = a_s[kk][ty * 4 + r];
            #pragma unroll
            for (int c = 0; c < 4; c++) br[c] = b_s[kk][tx * 4 + c];
            #pragma unroll
            for (int r = 0; r < 4; r++)
                #pragma unroll
                for (int c = 0; c < 4; c++)
                    acc[r][c] = fmaf(ar[r], br[c], acc[r][c]);
        }
        __syncthreads();
    }

    #pragma unroll
    for (int r = 0; r < 4; r++) {
        int m = row0 + ty * 4 + r;
        #pragma unroll
        for (int c = 0; c < 4; c++) {
            int n = col0 + tx * 4 + c;
            float v = acc[r][c];
            if (BIAS) v += bias[n];
            if (SPLIT) {
                int b_ = m / Sc, s_ = m - b_ * Sc;
                int h_ = n >> 6, d_ = n & 63;      // HD = 64
                C[((b_ * Hc + h_) * Sc + s_) * HDc + d_] = v;
            } else {
                C[m * N + n] = v;
            }
        }
    }
}

// ---------------------------------------------------------------------------
// Causal flash attention, fp32. One CTA = 64 query rows of one (b,h).
// Tiles: Q[64][64], K[64][64], V[64][64], S/P[64][64] in dynamic smem
// (all padded to stride 65 for conflict-free access). Online softmax.
// ---------------------------------------------------------------------------
#define ATTN_SMEM_FLOATS (4*64*65 + 3*64)

__global__ __launch_bounds__(256)
void attn_kernel(const float* __restrict__ q,
                 const float* __restrict__ k,
                 const float* __restrict__ v,
                 float* __restrict__ ctx) {
    extern __shared__ float sm[];
    float* q_s  = sm;               // [64][65]
    float* k_s  = sm + 4160;        // [64][65]
    float* v_s  = sm + 8320;        // [64][65]
    float* s_s  = sm + 12480;       // [64][65]
    float* m_s  = sm + 16640;       // [64]
    float* l_s  = sm + 16704;       // [64]
    float* sc_s = sm + 16768;       // [64]

    const int qb = blockIdx.x;      // query tile
    const int h  = blockIdx.y;
    const int b  = blockIdx.z;

    const float* qp    = q + ((size_t)(b * Hc + h) * Sc + qb * 64) * HDc;
    const float* kbase = k + (size_t)(b * Hc + h) * Sc * HDc;
    const float* vbase = v + (size_t)(b * Hc + h) * Sc * HDc;

    const int tid = threadIdx.x;
    const int tx = tid & 15;        // key/col group
    const int ty = tid >> 4;        // query/row group

    // Load Q tile (64x64)
    #pragma unroll
    for (int l = 0; l < 16; l++) {
        int idx = tid + l * 256;
        int r = idx >> 6, c = idx & 63;
        q_s[r * 65 + c] = qp[idx];
    }
    if (tid < 64) { m_s[tid] = -1e30f; l_s[tid] = 0.0f; }

    float acc[4][4] = {};
    __syncthreads();

    for (int jb = 0; jb <= qb; jb++) {
        const float* kp = kbase + (size_t)jb * 64 * HDc;
        const float* vp = vbase + (size_t)jb * 64 * HDc;
        #pragma unroll
        for (int l = 0; l < 16; l++) {
            int idx = tid + l * 256;
            int r = idx >> 6, c = idx & 63;
            k_s[r * 65 + c] = kp[idx];
            v_s[r * 65 + c] = vp[idx];
        }
        __syncthreads();

        // S = (Q @ K^T) * 1/sqrt(64), thread computes 4x4
        float s[4][4] = {};
        #pragma unroll 8
        for (int d = 0; d < 64; d++) {
            float qr[4], kr[4];
            #pragma unroll
            for (int r = 0; r < 4; r++) qr[r] = q_s[(ty * 4 + r) * 65 + d];
            #pragma unroll
            for (int c = 0; c < 4; c++) kr[c] = k_s[(tx * 4 + c) * 65 + d];
            #pragma unroll
            for (int r = 0; r < 4; r++)
                #pragma unroll
                for (int c = 0; c < 4; c++)
                    s[r][c] = fmaf(qr[r], kr[c], s[r][c]);
        }
        // mask + store scores
        #pragma unroll
        for (int r = 0; r < 4; r++) {
            int gq = qb * 64 + ty * 4 + r;
            #pragma unroll
            for (int c = 0; c < 4; c++) {
                int gk = jb * 64 + tx * 4 + c;
                float val = s[r][c] * 0.125f;
                if (gk > gq) val = -1e30f;
                s_s[(ty * 4 + r) * 65 + (tx * 4 + c)] = val;
            }
        }
        __syncthreads();

        // Online softmax, one thread per row (tid < 64)
        if (tid < 64) {
            const int r = tid;
            float m_old = m_s[r];
            float mx = m_old;
            #pragma unroll 8
            for (int j = 0; j < 64; j++) mx = fmaxf(mx, s_s[r * 65 + j]);
            float scale = __expf(m_old - mx);
            float sum = 0.0f;
            #pragma unroll 8
            for (int j = 0; j < 64; j++) {
                float p = __expf(s_s[r * 65 + j] - mx);
                s_s[r * 65 + j] = p;
                sum += p;
            }
            m_s[r] = mx;
            l_s[r] = l_s[r] * scale + sum;
            sc_s[r] = scale;
        }
        __syncthreads();

        // Rescale accumulator, then O += P @ V
        float rs[4];
        #pragma unroll
        for (int r = 0; r < 4; r++) rs[r] = sc_s[ty * 4 + r];
        #pragma unroll
        for (int r = 0; r < 4; r++)
            #pragma unroll
            for (int c = 0; c < 4; c++)
                acc[r][c] *= rs[r];

        #pragma unroll 8
        for (int j = 0; j < 64; j++) {
            float pr[4], vr[4];
            #pragma unroll
            for (int r = 0; r < 4; r++) pr[r] = s_s[(ty * 4 + r) * 65 + j];
            #pragma unroll
            for (int c = 0; c < 4; c++) vr[c] = v_s[j * 65 + (tx * 4 + c)];
            #pragma unroll
            for (int r = 0; r < 4; r++)
                #pragma unroll
                for (int c = 0; c < 4; c++)
                    acc[r][c] = fmaf(pr[r], vr[c], acc[r][c]);
        }
        __syncthreads();   // protect k_s/v_s/s_s for next iter
    }

    // Epilogue: divide by l, write ctx[b][s][h*64 + d]
    #pragma unroll
    for (int r = 0; r < 4; r++) {
        int gq = qb * 64 + ty * 4 + r;
        float inv = 1.0f / l_s[ty * 4 + r];
        #pragma unroll
        for (int c = 0; c < 4; c++) {
            ctx[((size_t)b * Sc + gq) * DOUT + h * HDc + tx * 4 + c] = acc[r][c] * inv;
        }
    }
}

// ---------------------------------------------------------------------------
extern "C" void kernel_launch(void* const* d_in, const int* in_sizes, int n_in,
                              void* d_out, int out_size) {
    const float* x  = (const float*)d_in[0];
    const float* Wq = (const float*)d_in[1];
    const float* Wk = (const float*)d_in[2];
    const float* Wv = (const float*)d_in[3];
    const float* Wo = (const float*)d_in[4];
    const float* bo = (const float*)d_in[5];
    float* out = (float*)d_out;

    float *q, *k, *v, *ctx;
    cudaGetSymbolAddress((void**)&q,   g_q);
    cudaGetSymbolAddress((void**)&k,   g_k);
    cudaGetSymbolAddress((void**)&v,   g_v);
    cudaGetSymbolAddress((void**)&ctx, g_ctx);

    const int attn_smem = ATTN_SMEM_FLOATS * sizeof(float);  // 67328 bytes
    cudaFuncSetAttribute(attn_kernel,
                         cudaFuncAttributeMaxDynamicSharedMemorySize, attn_smem);

    dim3 gg(DOUT / 64, MROWS / 64);   // (16, 128)

    gemm_kernel<true,  false><<<gg, 256>>>(x,   Wq, nullptr, q);
    gemm_kernel<true,  false><<<gg, 256>>>(x,   Wk, nullptr, k);
    gemm_kernel<true,  false><<<gg, 256>>>(x,   Wv, nullptr, v);

    attn_kernel<<<dim3(Sc / 64, Hc, Bc), 256, attn_smem>>>(q, k, v, ctx);

    gemm_kernel<false, true><<<gg, 256>>>(ctx, Wo, bo, out);
}

// round 3
// speedup vs baseline: 3.4696x; 3.4696x over previous
#include <cuda_runtime.h>
#include <math.h>

#define Bc   4
#define Sc   2048
#define DIN  1024
#define DOUT 1024
#define Hc   16
#define HDc  64
#define MROWS (Bc*Sc)   // 8192

// Scratch (device globals: allocation-free per harness rules)
__device__ float g_q[Bc*Hc*Sc*HDc];
__device__ float g_k[Bc*Hc*Sc*HDc];
__device__ float g_v[Bc*Hc*Sc*HDc];
__device__ float g_ctx[Bc*Sc*DOUT];

// ---------------------------------------------------------------------------
// tf32 helpers
// ---------------------------------------------------------------------------
__device__ __forceinline__ float to_tf32(float x) {
    float r;
    asm("cvt.rna.tf32.f32 %0, %1;" : "=f"(r) : "f"(x));
    return r;
}

__device__ __forceinline__ void mma_m16n8k8(float d[4], const unsigned a[4],
                                            const unsigned b[2], const float c[4]) {
    asm volatile(
        "mma.sync.aligned.m16n8k8.row.col.f32.tf32.tf32.f32 "
        "{%0,%1,%2,%3}, {%4,%5,%6,%7}, {%8,%9}, {%10,%11,%12,%13};\n"
        : "=f"(d[0]), "=f"(d[1]), "=f"(d[2]), "=f"(d[3])
        : "r"(a[0]), "r"(a[1]), "r"(a[2]), "r"(a[3]),
          "r"(b[0]), "r"(b[1]),
          "f"(c[0]), "f"(c[1]), "f"(c[2]), "f"(c[3]));
}

// ---------------------------------------------------------------------------
// TF32 tensor-core GEMM: C[M,N] = A[M,K] @ W[K,N] (+bias). M=8192, K=N=1024.
// Block tile 128x128, BK=32, 256 threads (8 warps), warp tile 32x64.
// SPLIT: scatter output into [B,H,S,HD] layout (q/k/v projections).
// ---------------------------------------------------------------------------
#define AS_STRIDE 36
#define BS_STRIDE 136

template<bool SPLIT, bool BIAS>
__global__ __launch_bounds__(256)
void gemm_tc(const float* __restrict__ A,
             const float* __restrict__ W,
             const float* __restrict__ bias,
             float* __restrict__ C) {
    __shared__ float a_s[128 * AS_STRIDE];   // [row][k]
    __shared__ float b_s[32 * BS_STRIDE];    // [k][n]

    const int tid  = threadIdx.x;
    const int warp = tid >> 5, lane = tid & 31;
    const int wm = warp >> 1, wn = warp & 1;       // 4 x 2 warp grid
    const int gid = lane >> 2, tig = lane & 3;

    const int row0 = blockIdx.y * 128;
    const int col0 = blockIdx.x * 128;

    float acc[2][8][4] = {};

    for (int k0 = 0; k0 < DIN; k0 += 32) {
        // Load A tile 128x32 (converted to tf32 at store)
        #pragma unroll
        for (int l = 0; l < 4; l++) {
            int lin = tid + l * 256;
            int r = lin >> 3, c = (lin & 7) * 4;
            float4 t = *(const float4*)&A[(size_t)(row0 + r) * DIN + k0 + c];
            float* d = &a_s[r * AS_STRIDE + c];
            d[0] = to_tf32(t.x); d[1] = to_tf32(t.y);
            d[2] = to_tf32(t.z); d[3] = to_tf32(t.w);
        }
        // Load W tile 32x128
        #pragma unroll
        for (int l = 0; l < 4; l++) {
            int lin = tid + l * 256;
            int r = lin >> 5, c = (lin & 31) * 4;
            float4 t = *(const float4*)&W[(size_t)(k0 + r) * DOUT + col0 + c];
            float* d = &b_s[r * BS_STRIDE + c];
            d[0] = to_tf32(t.x); d[1] = to_tf32(t.y);
            d[2] = to_tf32(t.z); d[3] = to_tf32(t.w);
        }
        __syncthreads();

        #pragma unroll
        for (int kk = 0; kk < 4; kk++) {
            unsigned af[2][4];
            #pragma unroll
            for (int i = 0; i < 2; i++) {
                int rb = wm * 32 + i * 16 + gid;
                int cb = kk * 8 + tig;
                af[i][0] = __float_as_uint(a_s[rb * AS_STRIDE + cb]);
                af[i][1] = __float_as_uint(a_s[(rb + 8) * AS_STRIDE + cb]);
                af[i][2] = __float_as_uint(a_s[rb * AS_STRIDE + cb + 4]);
                af[i][3] = __float_as_uint(a_s[(rb + 8) * AS_STRIDE + cb + 4]);
            }
            #pragma unroll
            for (int j = 0; j < 8; j++) {
                unsigned bf[2];
                int col = wn * 64 + j * 8 + gid;
                bf[0] = __float_as_uint(b_s[(kk * 8 + tig) * BS_STRIDE + col]);
                bf[1] = __float_as_uint(b_s[(kk * 8 + tig + 4) * BS_STRIDE + col]);
                #pragma unroll
                for (int i = 0; i < 2; i++)
                    mma_m16n8k8(acc[i][j], af[i], bf, acc[i][j]);
            }
        }
        __syncthreads();
    }

    // Epilogue
    #pragma unroll
    for (int i = 0; i < 2; i++) {
        #pragma unroll
        for (int j = 0; j < 8; j++) {
            #pragma unroll
            for (int r = 0; r < 4; r++) {
                int m = row0 + wm * 32 + i * 16 + gid + ((r >= 2) ? 8 : 0);
                int n = col0 + wn * 64 + j * 8 + tig * 2 + (r & 1);
                float v = acc[i][j][r];
                if (BIAS) v += bias[n];
                if (SPLIT) {
                    int b_ = m >> 11, s_ = m & 2047;
                    int h_ = n >> 6,  d_ = n & 63;
                    C[(((size_t)b_ * Hc + h_) * Sc + s_) * HDc + d_] = v;
                } else {
                    C[(size_t)m * DOUT + n] = v;
                }
            }
        }
    }
}

// ---------------------------------------------------------------------------
// Causal flash attention with tf32 mma. One CTA = 64 query rows of one (b,h).
// 64x64 Q/K/V/S tiles in dynamic smem (stride 68). 8 warps: warp tile 16x32
// for both S=QK^T and O+=PV. Online softmax, 4 threads per row.
// ---------------------------------------------------------------------------
#define TS 68
#define ATTN_SMEM_FLOATS (4*64*TS + 3*64)

__global__ __launch_bounds__(256)
void attn_tc(const float* __restrict__ q,
             const float* __restrict__ k,
             const float* __restrict__ v,
             float* __restrict__ ctx) {
    extern __shared__ float sm[];
    float* q_s  = sm;                 // [64][TS]
    float* k_s  = sm + 64 * TS;
    float* v_s  = sm + 2 * 64 * TS;
    float* s_s  = sm + 3 * 64 * TS;
    float* m_s  = sm + 4 * 64 * TS;
    float* l_s  = m_s + 64;
    float* sc_s = l_s + 64;

    const int qb = blockIdx.x;
    const int h  = blockIdx.y;
    const int b  = blockIdx.z;

    const float* qp    = q + ((size_t)(b * Hc + h) * Sc + qb * 64) * HDc;
    const float* kbase = k + (size_t)(b * Hc + h) * Sc * HDc;
    const float* vbase = v + (size_t)(b * Hc + h) * Sc * HDc;

    const int tid  = threadIdx.x;
    const int warp = tid >> 5, lane = tid & 31;
    const int wm = warp >> 1, wn = warp & 1;   // 4 x 2 warp grid: 16 rows x 32 cols
    const int gid = lane >> 2, tig = lane & 3;

    // Load Q tile (tf32-converted)
    #pragma unroll
    for (int l = 0; l < 4; l++) {
        int lin = tid + l * 256;
        int r = lin >> 4, c = (lin & 15) * 4;
        float4 t = *(const float4*)&qp[r * HDc + c];
        float* d = &q_s[r * TS + c];
        d[0] = to_tf32(t.x); d[1] = to_tf32(t.y);
        d[2] = to_tf32(t.z); d[3] = to_tf32(t.w);
    }
    if (tid < 64) { m_s[tid] = -1e30f; l_s[tid] = 0.0f; }

    float o_acc[4][4] = {};    // 4 n-tiles x 4 regs
    __syncthreads();

    for (int jb = 0; jb <= qb; jb++) {
        const float* kp = kbase + (size_t)jb * 64 * HDc;
        const float* vp = vbase + (size_t)jb * 64 * HDc;
        #pragma unroll
        for (int l = 0; l < 4; l++) {
            int lin = tid + l * 256;
            int r = lin >> 4, c = (lin & 15) * 4;
            float4 tk = *(const float4*)&kp[r * HDc + c];
            float4 tv = *(const float4*)&vp[r * HDc + c];
            float* dk = &k_s[r * TS + c];
            float* dv = &v_s[r * TS + c];
            dk[0] = to_tf32(tk.x); dk[1] = to_tf32(tk.y);
            dk[2] = to_tf32(tk.z); dk[3] = to_tf32(tk.w);
            dv[0] = to_tf32(tv.x); dv[1] = to_tf32(tv.y);
            dv[2] = to_tf32(tv.z); dv[3] = to_tf32(tv.w);
        }
        __syncthreads();

        // ----- S = Q @ K^T (warp tile 16x32 => 4 n-tiles) -----
        float s_acc[4][4] = {};
        #pragma unroll
        for (int kk = 0; kk < 8; kk++) {
            unsigned af[4];
            int rb = wm * 16 + gid;
            int cb = kk * 8 + tig;
            af[0] = __float_as_uint(q_s[rb * TS + cb]);
            af[1] = __float_as_uint(q_s[(rb + 8) * TS + cb]);
            af[2] = __float_as_uint(q_s[rb * TS + cb + 4]);
            af[3] = __float_as_uint(q_s[(rb + 8) * TS + cb + 4]);
            #pragma unroll
            for (int j = 0; j < 4; j++) {
                unsigned bf[2];
                int key = wn * 32 + j * 8 + gid;
                bf[0] = __float_as_uint(k_s[key * TS + kk * 8 + tig]);
                bf[1] = __float_as_uint(k_s[key * TS + kk * 8 + tig + 4]);
                mma_m16n8k8(s_acc[j], af, bf, s_acc[j]);
            }
        }

        // scale + causal mask + store to smem
        const bool diag = (jb == qb);
        #pragma unroll
        for (int j = 0; j < 4; j++) {
            #pragma unroll
            for (int r = 0; r < 4; r++) {
                int rl = wm * 16 + gid + ((r >= 2) ? 8 : 0);
                int cl = wn * 32 + j * 8 + tig * 2 + (r & 1);
                float val = s_acc[j][r] * 0.125f;
                if (diag && (jb * 64 + cl) > (qb * 64 + rl)) val = -1e30f;
                s_s[rl * TS + cl] = val;
            }
        }
        __syncthreads();

        // ----- online softmax: 4 threads per row -----
        {
            int r  = tid >> 2;
            int q4 = tid & 3;
            float* row = &s_s[r * TS + q4 * 16];
            float m_old = m_s[r];
            float mx = m_old;
            #pragma unroll
            for (int jj = 0; jj < 16; jj++) mx = fmaxf(mx, row[jj]);
            mx = fmaxf(mx, __shfl_xor_sync(0xFFFFFFFF, mx, 1));
            mx = fmaxf(mx, __shfl_xor_sync(0xFFFFFFFF, mx, 2));
            float sum = 0.0f;
            #pragma unroll
            for (int jj = 0; jj < 16; jj++) {
                float p = __expf(row[jj] - mx);
                sum += p;
                row[jj] = to_tf32(p);     // pre-convert P for the PV mma
            }
            sum += __shfl_xor_sync(0xFFFFFFFF, sum, 1);
            sum += __shfl_xor_sync(0xFFFFFFFF, sum, 2);
            if (q4 == 0) {
                float scale = __expf(m_old - mx);
                m_s[r]  = mx;
                l_s[r]  = l_s[r] * scale + sum;
                sc_s[r] = scale;
            }
        }
        __syncthreads();

        // ----- rescale O, then O += P @ V -----
        {
            float sc0 = sc_s[wm * 16 + gid];
            float sc1 = sc_s[wm * 16 + gid + 8];
            #pragma unroll
            for (int j = 0; j < 4; j++) {
                o_acc[j][0] *= sc0; o_acc[j][1] *= sc0;
                o_acc[j][2] *= sc1; o_acc[j][3] *= sc1;
            }
        }
        #pragma unroll
        for (int kk = 0; kk < 8; kk++) {
            unsigned af[4];
            int rb = wm * 16 + gid;
            int cb = kk * 8 + tig;
            af[0] = __float_as_uint(s_s[rb * TS + cb]);
            af[1] = __float_as_uint(s_s[(rb + 8) * TS + cb]);
            af[2] = __float_as_uint(s_s[rb * TS + cb + 4]);
            af[3] = __float_as_uint(s_s[(rb + 8) * TS + cb + 4]);
            #pragma unroll
            for (int j = 0; j < 4; j++) {
                unsigned bf[2];
                int d = wn * 32 + j * 8 + gid;
                bf[0] = __float_as_uint(v_s[(kk * 8 + tig) * TS + d]);
                bf[1] = __float_as_uint(v_s[(kk * 8 + tig + 4) * TS + d]);
                mma_m16n8k8(o_acc[j], af, bf, o_acc[j]);
            }
        }
        __syncthreads();   // protect k_s/v_s/s_s for next iteration
    }

    // Epilogue: O /= l, write ctx[b][s][h*64+d]
    {
        float inv0 = 1.0f / l_s[wm * 16 + gid];
        float inv1 = 1.0f / l_s[wm * 16 + gid + 8];
        int gq0 = qb * 64 + wm * 16 + gid;
        #pragma unroll
        for (int j = 0; j < 4; j++) {
            int cl = h * HDc + wn * 32 + j * 8 + tig * 2;
            float* o0 = &ctx[((size_t)b * Sc + gq0) * DOUT + cl];
            float* o1 = &ctx[((size_t)b * Sc + gq0 + 8) * DOUT + cl];
            o0[0] = o_acc[j][0] * inv0; o0[1] = o_acc[j][1] * inv0;
            o1[0] = o_acc[j][2] * inv1; o1[1] = o_acc[j][3] * inv1;
        }
    }
}

// ---------------------------------------------------------------------------
extern "C" void kernel_launch(void* const* d_in, const int* in_sizes, int n_in,
                              void* d_out, int out_size) {
    const float* x  = (const float*)d_in[0];
    const float* Wq = (const float*)d_in[1];
    const float* Wk = (const float*)d_in[2];
    const float* Wv = (const float*)d_in[3];
    const float* Wo = (const float*)d_in[4];
    const float* bo = (const float*)d_in[5];
    float* out = (float*)d_out;

    float *q, *k, *v, *ctx;
    cudaGetSymbolAddress((void**)&q,   g_q);
    cudaGetSymbolAddress((void**)&k,   g_k);
    cudaGetSymbolAddress((void**)&v,   g_v);
    cudaGetSymbolAddress((void**)&ctx, g_ctx);

    const int attn_smem = ATTN_SMEM_FLOATS * sizeof(float);  // 70400 bytes
    cudaFuncSetAttribute(attn_tc,
                         cudaFuncAttributeMaxDynamicSharedMemorySize, attn_smem);

    dim3 gg(DOUT / 128, MROWS / 128);   // (8, 64)

    gemm_tc<true,  false><<<gg, 256>>>(x,   Wq, nullptr, q);
    gemm_tc<true,  false><<<gg, 256>>>(x,   Wk, nullptr, k);
    gemm_tc<true,  false><<<gg, 256>>>(x,   Wv, nullptr, v);

    attn_tc<<<dim3(Sc / 64, Hc, Bc), 256, attn_smem>>>(q, k, v, ctx);

    gemm_tc<false, true><<<gg, 256>>>(ctx, Wo, bo, out);
}

// round 4
// speedup vs baseline: 3.5599x; 1.0260x over previous
#include <cuda_runtime.h>
#include <math.h>

#define Bc   4
#define Sc   2048
#define DIN  1024
#define DOUT 1024
#define Hc   16
#define HDc  64
#define MROWS (Bc*Sc)   // 8192

// Scratch (device globals: allocation-free per harness rules)
__device__ float g_q[Bc*Hc*Sc*HDc];
__device__ float g_k[Bc*Hc*Sc*HDc];
__device__ float g_v[Bc*Hc*Sc*HDc];
__device__ float g_ctx[Bc*Sc*DOUT];

// ---------------------------------------------------------------------------
// tf32 helpers
// ---------------------------------------------------------------------------
__device__ __forceinline__ float to_tf32(float x) {
    float r;
    asm("cvt.rna.tf32.f32 %0, %1;" : "=f"(r) : "f"(x));
    return r;
}

__device__ __forceinline__ void mma_m16n8k8(float d[4], const unsigned a[4],
                                            const unsigned b[2], const float c[4]) {
    asm volatile(
        "mma.sync.aligned.m16n8k8.row.col.f32.tf32.tf32.f32 "
        "{%0,%1,%2,%3}, {%4,%5,%6,%7}, {%8,%9}, {%10,%11,%12,%13};\n"
        : "=f"(d[0]), "=f"(d[1]), "=f"(d[2]), "=f"(d[3])
        : "r"(a[0]), "r"(a[1]), "r"(a[2]), "r"(a[3]),
          "r"(b[0]), "r"(b[1]),
          "f"(c[0]), "f"(c[1]), "f"(c[2]), "f"(c[3]));
}

// ---------------------------------------------------------------------------
// TF32 tensor-core GEMM with register-staged prefetch.
// C[M,N] = A[M,K] @ W[K,N] (+bias). Block tile 128x128, BK=32, 8 warps,
// warp tile 32x64. SPLIT: scatter into [B,H,S,HD].
// ---------------------------------------------------------------------------
#define AS_STRIDE 36
#define BS_STRIDE 136

template<bool SPLIT, bool BIAS>
__global__ __launch_bounds__(256)
void gemm_tc(const float* __restrict__ A,
             const float* __restrict__ W,
             const float* __restrict__ bias,
             float* __restrict__ C) {
    __shared__ float a_s[128 * AS_STRIDE];   // [row][k]
    __shared__ float b_s[32 * BS_STRIDE];    // [k][n]

    const int tid  = threadIdx.x;
    const int warp = tid >> 5, lane = tid & 31;
    const int wm = warp >> 1, wn = warp & 1;       // 4 x 2 warp grid
    const int gid = lane >> 2, tig = lane & 3;

    const int row0 = blockIdx.y * 128;
    const int col0 = blockIdx.x * 128;

    float acc[2][8][4] = {};
    float4 pa[4], pb[4];

    // prologue: load tile 0
    #pragma unroll
    for (int l = 0; l < 4; l++) {
        int lin = tid + l * 256;
        pa[l] = *(const float4*)&A[(size_t)(row0 + (lin >> 3)) * DIN + ((lin & 7) * 4)];
        pb[l] = *(const float4*)&W[(size_t)(lin >> 5) * DOUT + col0 + ((lin & 31) * 4)];
    }
    #pragma unroll
    for (int l = 0; l < 4; l++) {
        int lin = tid + l * 256;
        float4 ta = make_float4(to_tf32(pa[l].x), to_tf32(pa[l].y), to_tf32(pa[l].z), to_tf32(pa[l].w));
        *(float4*)&a_s[(lin >> 3) * AS_STRIDE + (lin & 7) * 4] = ta;
        float4 tb = make_float4(to_tf32(pb[l].x), to_tf32(pb[l].y), to_tf32(pb[l].z), to_tf32(pb[l].w));
        *(float4*)&b_s[(lin >> 5) * BS_STRIDE + (lin & 31) * 4] = tb;
    }
    __syncthreads();

    for (int k0 = 32; k0 <= DIN; k0 += 32) {
        const bool has_next = (k0 < DIN);
        if (has_next) {
            #pragma unroll
            for (int l = 0; l < 4; l++) {
                int lin = tid + l * 256;
                pa[l] = *(const float4*)&A[(size_t)(row0 + (lin >> 3)) * DIN + k0 + ((lin & 7) * 4)];
                pb[l] = *(const float4*)&W[(size_t)(k0 + (lin >> 5)) * DOUT + col0 + ((lin & 31) * 4)];
            }
        }

        #pragma unroll
        for (int kk = 0; kk < 4; kk++) {
            unsigned af[2][4];
            #pragma unroll
            for (int i = 0; i < 2; i++) {
                int rb = wm * 32 + i * 16 + gid;
                int cb = kk * 8 + tig;
                af[i][0] = __float_as_uint(a_s[rb * AS_STRIDE + cb]);
                af[i][1] = __float_as_uint(a_s[(rb + 8) * AS_STRIDE + cb]);
                af[i][2] = __float_as_uint(a_s[rb * AS_STRIDE + cb + 4]);
                af[i][3] = __float_as_uint(a_s[(rb + 8) * AS_STRIDE + cb + 4]);
            }
            #pragma unroll
            for (int j = 0; j < 8; j++) {
                unsigned bf[2];
                int col = wn * 64 + j * 8 + gid;
                bf[0] = __float_as_uint(b_s[(kk * 8 + tig) * BS_STRIDE + col]);
                bf[1] = __float_as_uint(b_s[(kk * 8 + tig + 4) * BS_STRIDE + col]);
                #pragma unroll
                for (int i = 0; i < 2; i++)
                    mma_m16n8k8(acc[i][j], af[i], bf, acc[i][j]);
            }
        }

        if (has_next) {
            __syncthreads();
            #pragma unroll
            for (int l = 0; l < 4; l++) {
                int lin = tid + l * 256;
                float4 ta = make_float4(to_tf32(pa[l].x), to_tf32(pa[l].y), to_tf32(pa[l].z), to_tf32(pa[l].w));
                *(float4*)&a_s[(lin >> 3) * AS_STRIDE + (lin & 7) * 4] = ta;
                float4 tb = make_float4(to_tf32(pb[l].x), to_tf32(pb[l].y), to_tf32(pb[l].z), to_tf32(pb[l].w));
                *(float4*)&b_s[(lin >> 5) * BS_STRIDE + (lin & 31) * 4] = tb;
            }
            __syncthreads();
        }
    }

    // Epilogue (float2 stores: cols tig*2, tig*2+1 adjacent)
    #pragma unroll
    for (int i = 0; i < 2; i++) {
        #pragma unroll
        for (int rr = 0; rr < 2; rr++) {     // rr=0 -> regs 0,1 ; rr=1 -> regs 2,3
            int m = row0 + wm * 32 + i * 16 + gid + rr * 8;
            #pragma unroll
            for (int j = 0; j < 8; j++) {
                int n = col0 + wn * 64 + j * 8 + tig * 2;
                float v0 = acc[i][j][rr * 2 + 0];
                float v1 = acc[i][j][rr * 2 + 1];
                if (BIAS) { v0 += bias[n]; v1 += bias[n + 1]; }
                if (SPLIT) {
                    int b_ = m >> 11, s_ = m & 2047;
                    int h_ = n >> 6,  d_ = n & 63;
                    *(float2*)&C[(((size_t)b_ * Hc + h_) * Sc + s_) * HDc + d_] =
                        make_float2(v0, v1);
                } else {
                    *(float2*)&C[(size_t)m * DOUT + n] = make_float2(v0, v1);
                }
            }
        }
    }
}

// ---------------------------------------------------------------------------
// Causal flash attention, tf32 mma. CTA = 128 queries, 8 warps, warp tile
// 16x64 (each warp owns full S rows). Softmax in registers + shfl.
// P -> A-fragment relayout via shfl (no smem roundtrip for S).
// ---------------------------------------------------------------------------
#define QT 128
#define KT 64
#define TS 68
#define ATTN_SMEM_FLOATS ((QT + 2*KT) * TS)   // 17408 floats = 69632 B

__global__ __launch_bounds__(256, 2)
void attn_tc(const float* __restrict__ q,
             const float* __restrict__ k,
             const float* __restrict__ v,
             float* __restrict__ ctx) {
    extern __shared__ float sm[];
    float* q_s = sm;                       // [128][TS]
    float* k_s = sm + QT * TS;             // [64][TS]
    float* v_s = sm + (QT + KT) * TS;      // [64][TS]

    const int qb = (gridDim.x - 1) - blockIdx.x;   // heavy tiles first
    const int h  = blockIdx.y;
    const int b  = blockIdx.z;
    const int q0 = qb * QT;

    const float* qp    = q + ((size_t)(b * Hc + h) * Sc + q0) * HDc;
    const float* kbase = k + (size_t)(b * Hc + h) * Sc * HDc;
    const float* vbase = v + (size_t)(b * Hc + h) * Sc * HDc;

    const int tid  = threadIdx.x;
    const int warp = tid >> 5, lane = tid & 31;
    const int gid = lane >> 2, tig = lane & 3;

    // Load Q tile 128x64 (tf32, float4 stores)
    #pragma unroll
    for (int l = 0; l < 8; l++) {
        int lin = tid + l * 256;
        int r = lin >> 4, c = (lin & 15) * 4;
        float4 t = *(const float4*)&qp[r * HDc + c];
        *(float4*)&q_s[r * TS + c] =
            make_float4(to_tf32(t.x), to_tf32(t.y), to_tf32(t.z), to_tf32(t.w));
    }

    // Per-thread softmax state: rows warp*16+gid (lo) and +8 (hi)
    float m_lo = -1e30f, m_hi = -1e30f, l_lo = 0.0f, l_hi = 0.0f;
    float o[8][4] = {};    // 8 col-frags x 4 regs

    __syncthreads();

    const int jb_end = 2 * qb + 1;
    for (int jb = 0; jb <= jb_end; jb++) {
        const float* kp = kbase + (size_t)jb * KT * HDc;
        const float* vp = vbase + (size_t)jb * KT * HDc;
        #pragma unroll
        for (int l = 0; l < 4; l++) {
            int lin = tid + l * 256;
            int r = lin >> 4, c = (lin & 15) * 4;
            float4 tk = *(const float4*)&kp[r * HDc + c];
            float4 tv = *(const float4*)&vp[r * HDc + c];
            *(float4*)&k_s[r * TS + c] =
                make_float4(to_tf32(tk.x), to_tf32(tk.y), to_tf32(tk.z), to_tf32(tk.w));
            *(float4*)&v_s[r * TS + c] =
                make_float4(to_tf32(tv.x), to_tf32(tv.y), to_tf32(tv.z), to_tf32(tv.w));
        }
        __syncthreads();

        // ----- S = Q @ K^T : warp tile 16x64 -----
        float s_acc[8][4] = {};
        #pragma unroll
        for (int kk = 0; kk < 8; kk++) {
            unsigned af[4];
            int rb = warp * 16 + gid;
            int cb = kk * 8 + tig;
            af[0] = __float_as_uint(q_s[rb * TS + cb]);
            af[1] = __float_as_uint(q_s[(rb + 8) * TS + cb]);
            af[2] = __float_as_uint(q_s[rb * TS + cb + 4]);
            af[3] = __float_as_uint(q_s[(rb + 8) * TS + cb + 4]);
            #pragma unroll
            for (int j = 0; j < 8; j++) {
                unsigned bf[2];
                int key = j * 8 + gid;
                bf[0] = __float_as_uint(k_s[key * TS + kk * 8 + tig]);
                bf[1] = __float_as_uint(k_s[key * TS + kk * 8 + tig + 4]);
                mma_m16n8k8(s_acc[j], af, bf, s_acc[j]);
            }
        }

        // ----- scale + causal mask (registers) -----
        const int row_lo = q0 + warp * 16 + gid;
        const int row_hi = row_lo + 8;
        const bool domask = (jb >= 2 * qb);
        #pragma unroll
        for (int j = 0; j < 8; j++) {
            #pragma unroll
            for (int r = 0; r < 4; r++) {
                float val = s_acc[j][r] * 0.125f;
                if (domask) {
                    int col = jb * KT + j * 8 + tig * 2 + (r & 1);
                    int row = (r >= 2) ? row_hi : row_lo;
                    if (col > row) val = -1e30f;
                }
                s_acc[j][r] = val;
            }
        }

        // ----- online softmax in registers (row fully in-warp) -----
        float mx_lo = -1e30f, mx_hi = -1e30f;
        #pragma unroll
        for (int j = 0; j < 8; j++) {
            mx_lo = fmaxf(mx_lo, fmaxf(s_acc[j][0], s_acc[j][1]));
            mx_hi = fmaxf(mx_hi, fmaxf(s_acc[j][2], s_acc[j][3]));
        }
        mx_lo = fmaxf(mx_lo, __shfl_xor_sync(0xFFFFFFFF, mx_lo, 1));
        mx_lo = fmaxf(mx_lo, __shfl_xor_sync(0xFFFFFFFF, mx_lo, 2));
        mx_hi = fmaxf(mx_hi, __shfl_xor_sync(0xFFFFFFFF, mx_hi, 1));
        mx_hi = fmaxf(mx_hi, __shfl_xor_sync(0xFFFFFFFF, mx_hi, 2));

        float mn_lo = fmaxf(m_lo, mx_lo);
        float mn_hi = fmaxf(m_hi, mx_hi);
        float sc_lo = __expf(m_lo - mn_lo);
        float sc_hi = __expf(m_hi - mn_hi);

        float sum_lo = 0.0f, sum_hi = 0.0f;
        #pragma unroll
        for (int j = 0; j < 8; j++) {
            float p0 = __expf(s_acc[j][0] - mn_lo);
            float p1 = __expf(s_acc[j][1] - mn_lo);
            float p2 = __expf(s_acc[j][2] - mn_hi);
            float p3 = __expf(s_acc[j][3] - mn_hi);
            sum_lo += p0 + p1;
            sum_hi += p2 + p3;
            s_acc[j][0] = to_tf32(p0);
            s_acc[j][1] = to_tf32(p1);
            s_acc[j][2] = to_tf32(p2);
            s_acc[j][3] = to_tf32(p3);
        }
        sum_lo += __shfl_xor_sync(0xFFFFFFFF, sum_lo, 1);
        sum_lo += __shfl_xor_sync(0xFFFFFFFF, sum_lo, 2);
        sum_hi += __shfl_xor_sync(0xFFFFFFFF, sum_hi, 1);
        sum_hi += __shfl_xor_sync(0xFFFFFFFF, sum_hi, 2);

        m_lo = mn_lo; m_hi = mn_hi;
        l_lo = l_lo * sc_lo + sum_lo;
        l_hi = l_hi * sc_hi + sum_hi;

        // rescale O
        #pragma unroll
        for (int j = 0; j < 8; j++) {
            o[j][0] *= sc_lo; o[j][1] *= sc_lo;
            o[j][2] *= sc_hi; o[j][3] *= sc_hi;
        }

        // ----- O += P @ V : P relayout via shfl (no smem roundtrip) -----
        const int sa = gid * 4 + (tig >> 1);       // source lane, cols kk*8+tig
        const int sb = sa + 2;                     // source lane, cols kk*8+tig+4
        const bool odd = (tig & 1);
        #pragma unroll
        for (int kk = 0; kk < 8; kk++) {
            float a0e = __shfl_sync(0xFFFFFFFF, s_acc[kk][0], sa);
            float a0o = __shfl_sync(0xFFFFFFFF, s_acc[kk][1], sa);
            float a1e = __shfl_sync(0xFFFFFFFF, s_acc[kk][2], sa);
            float a1o = __shfl_sync(0xFFFFFFFF, s_acc[kk][3], sa);
            float a2e = __shfl_sync(0xFFFFFFFF, s_acc[kk][0], sb);
            float a2o = __shfl_sync(0xFFFFFFFF, s_acc[kk][1], sb);
            float a3e = __shfl_sync(0xFFFFFFFF, s_acc[kk][2], sb);
            float a3o = __shfl_sync(0xFFFFFFFF, s_acc[kk][3], sb);
            unsigned af[4];
            af[0] = __float_as_uint(odd ? a0o : a0e);
            af[1] = __float_as_uint(odd ? a1o : a1e);
            af[2] = __float_as_uint(odd ? a2o : a2e);
            af[3] = __float_as_uint(odd ? a3o : a3e);
            #pragma unroll
            for (int j = 0; j < 8; j++) {
                unsigned bf[2];
                int d = j * 8 + gid;
                bf[0] = __float_as_uint(v_s[(kk * 8 + tig) * TS + d]);
                bf[1] = __float_as_uint(v_s[(kk * 8 + tig + 4) * TS + d]);
                mma_m16n8k8(o[j], af, bf, o[j]);
            }
        }
        __syncthreads();   // k_s/v_s consumed; safe to overwrite next iter
    }

    // ----- Epilogue: O /= l, write ctx[b][s][h*64+d] -----
    {
        float inv_lo = 1.0f / l_lo;
        float inv_hi = 1.0f / l_hi;
        int grow = q0 + warp * 16 + gid;
        #pragma unroll
        for (int j = 0; j < 8; j++) {
            int cl = h * HDc + j * 8 + tig * 2;
            *(float2*)&ctx[((size_t)b * Sc + grow) * DOUT + cl] =
                make_float2(o[j][0] * inv_lo, o[j][1] * inv_lo);
            *(float2*)&ctx[((size_t)b * Sc + grow + 8) * DOUT + cl] =
                make_float2(o[j][2] * inv_hi, o[j][3] * inv_hi);
        }
    }
}

// ---------------------------------------------------------------------------
extern "C" void kernel_launch(void* const* d_in, const int* in_sizes, int n_in,
                              void* d_out, int out_size) {
    const float* x  = (const float*)d_in[0];
    const float* Wq = (const float*)d_in[1];
    const float* Wk = (const float*)d_in[2];
    const float* Wv = (const float*)d_in[3];
    const float* Wo = (const float*)d_in[4];
    const float* bo = (const float*)d_in[5];
    float* out = (float*)d_out;

    float *q, *k, *v, *ctx;
    cudaGetSymbolAddress((void**)&q,   g_q);
    cudaGetSymbolAddress((void**)&k,   g_k);
    cudaGetSymbolAddress((void**)&v,   g_v);
    cudaGetSymbolAddress((void**)&ctx, g_ctx);

    const int attn_smem = ATTN_SMEM_FLOATS * sizeof(float);  // 69632 bytes
    cudaFuncSetAttribute(attn_tc,
                         cudaFuncAttributeMaxDynamicSharedMemorySize, attn_smem);

    dim3 gg(DOUT / 128, MROWS / 128);   // (8, 64)

    gemm_tc<true,  false><<<gg, 256>>>(x,   Wq, nullptr, q);
    gemm_tc<true,  false><<<gg, 256>>>(x,   Wk, nullptr, k);
    gemm_tc<true,  false><<<gg, 256>>>(x,   Wv, nullptr, v);

    attn_tc<<<dim3(Sc / QT, Hc, Bc), 256, attn_smem>>>(q, k, v, ctx);

    gemm_tc<false, true><<<gg, 256>>>(ctx, Wo, bo, out);
}

// round 5
// speedup vs baseline: 4.7003x; 1.3203x over previous
#include <cuda_runtime.h>
#include <math.h>
#include <stdint.h>

#define Bc   4
#define Sc   2048
#define DIN  1024
#define DOUT 1024
#define Hc   16
#define HDc  64
#define MROWS (Bc*Sc)   // 8192

// Scratch (device globals: allocation-free per harness rules)
__device__ float g_q[Bc*Hc*Sc*HDc];
__device__ float g_k[Bc*Hc*Sc*HDc];
__device__ float g_v[Bc*Hc*Sc*HDc];
__device__ float g_ctx[Bc*Sc*DOUT];
__device__ float g_xr[MROWS*DIN];       // tf32-rounded x
__device__ float g_wr[4*DIN*DOUT];      // tf32-rounded Wq,Wk,Wv,Wo

// ---------------------------------------------------------------------------
// helpers
// ---------------------------------------------------------------------------
__device__ __forceinline__ float to_tf32(float x) {
    float r;
    asm("cvt.rna.tf32.f32 %0, %1;" : "=f"(r) : "f"(x));
    return r;
}

__device__ __forceinline__ void mma_m16n8k8(float d[4], const unsigned a[4],
                                            const unsigned b[2], const float c[4]) {
    asm volatile(
        "mma.sync.aligned.m16n8k8.row.col.f32.tf32.tf32.f32 "
        "{%0,%1,%2,%3}, {%4,%5,%6,%7}, {%8,%9}, {%10,%11,%12,%13};\n"
        : "=f"(d[0]), "=f"(d[1]), "=f"(d[2]), "=f"(d[3])
        : "r"(a[0]), "r"(a[1]), "r"(a[2]), "r"(a[3]),
          "r"(b[0]), "r"(b[1]),
          "f"(c[0]), "f"(c[1]), "f"(c[2]), "f"(c[3]));
}

__device__ __forceinline__ void cp_async16(uint32_t smem_addr, const void* gptr) {
    asm volatile("cp.async.cg.shared.global [%0], [%1], 16;\n"
                 :: "r"(smem_addr), "l"(gptr));
}
__device__ __forceinline__ void cp_commit() {
    asm volatile("cp.async.commit_group;\n");
}
template<int N>
__device__ __forceinline__ void cp_wait() {
    asm volatile("cp.async.wait_group %0;\n" :: "n"(N));
}

// ---------------------------------------------------------------------------
// tf32 pre-round kernel (float4 granularity)
// ---------------------------------------------------------------------------
__global__ void round_tf32_kernel(const float* __restrict__ in,
                                  float* __restrict__ out, int n4) {
    int i = blockIdx.x * blockDim.x + threadIdx.x;
    if (i < n4) {
        float4 t = ((const float4*)in)[i];
        ((float4*)out)[i] = make_float4(to_tf32(t.x), to_tf32(t.y),
                                        to_tf32(t.z), to_tf32(t.w));
    }
}

// ---------------------------------------------------------------------------
// TF32 GEMM, cp.async 3-stage. C[8192,1024] = A @ W (+bias).
// CTA tile 128x128x32, 4 warps (128 thr), warp tile 64x64.
// Inputs must be pre-rounded to tf32. SPLIT: scatter to [B,H,S,HD] + round.
// ---------------------------------------------------------------------------
#define AS_STRIDE 36
#define BS_STRIDE 136
#define G_STAGE_A (128*AS_STRIDE)            // floats
#define G_STAGE_B (32*BS_STRIDE)
#define G_STAGE   (G_STAGE_A + G_STAGE_B)    // 8960 floats
#define G_SMEM_BYTES (3*G_STAGE*4)           // 107520 B

template<bool SPLIT, bool BIAS>
__global__ __launch_bounds__(128, 2)
void gemm_tc(const float* __restrict__ A,
             const float* __restrict__ W,
             const float* __restrict__ bias,
             float* __restrict__ C) {
    extern __shared__ float smem[];
    const uint32_t sbase = (uint32_t)__cvta_generic_to_shared(smem);

    const int tid  = threadIdx.x;
    const int warp = tid >> 5, lane = tid & 31;
    const int wm = warp >> 1, wn = warp & 1;    // 2x2 warp grid, 64x64 each
    const int gid = lane >> 2, tig = lane & 3;

    const int row0 = blockIdx.y * 128;
    const int col0 = blockIdx.x * 128;

    float acc[4][8][4] = {};

    // issue one k-tile into stage s
    auto issue = [&](int t, int s) {
        uint32_t abase = sbase + (uint32_t)(s * G_STAGE) * 4u;
        uint32_t bbase = abase + (uint32_t)G_STAGE_A * 4u;
        #pragma unroll
        for (int l = 0; l < 8; l++) {
            int lin = tid + l * 128;
            int ar = lin >> 3, ac = (lin & 7) * 4;
            cp_async16(abase + (uint32_t)(ar * AS_STRIDE + ac) * 4u,
                       &A[(size_t)(row0 + ar) * DIN + t * 32 + ac]);
            int br = lin >> 5, bc = (lin & 31) * 4;
            cp_async16(bbase + (uint32_t)(br * BS_STRIDE + bc) * 4u,
                       &W[(size_t)(t * 32 + br) * DOUT + col0 + bc]);
        }
        cp_commit();
    };

    issue(0, 0);
    issue(1, 1);

    const int NT = DIN / 32;   // 32
    for (int t = 0; t < NT; t++) {
        cp_wait<1>();
        __syncthreads();
        if (t + 2 < NT) issue(t + 2, (t + 2) % 3);

        const float* a_s = smem + (t % 3) * G_STAGE;
        const float* b_s = a_s + G_STAGE_A;

        #pragma unroll
        for (int kk = 0; kk < 4; kk++) {
            unsigned af[4][4];
            #pragma unroll
            for (int i = 0; i < 4; i++) {
                int rb = wm * 64 + i * 16 + gid;
                int cb = kk * 8 + tig;
                af[i][0] = __float_as_uint(a_s[rb * AS_STRIDE + cb]);
                af[i][1] = __float_as_uint(a_s[(rb + 8) * AS_STRIDE + cb]);
                af[i][2] = __float_as_uint(a_s[rb * AS_STRIDE + cb + 4]);
                af[i][3] = __float_as_uint(a_s[(rb + 8) * AS_STRIDE + cb + 4]);
            }
            #pragma unroll
            for (int j = 0; j < 8; j++) {
                unsigned bf[2];
                int col = wn * 64 + j * 8 + gid;
                bf[0] = __float_as_uint(b_s[(kk * 8 + tig) * BS_STRIDE + col]);
                bf[1] = __float_as_uint(b_s[(kk * 8 + tig + 4) * BS_STRIDE + col]);
                #pragma unroll
                for (int i = 0; i < 4; i++)
                    mma_m16n8k8(acc[i][j], af[i], bf, acc[i][j]);
            }
        }
        __syncthreads();
    }

    // Epilogue
    #pragma unroll
    for (int i = 0; i < 4; i++) {
        #pragma unroll
        for (int rr = 0; rr < 2; rr++) {
            int m = row0 + wm * 64 + i * 16 + gid + rr * 8;
            #pragma unroll
            for (int j = 0; j < 8; j++) {
                int n = col0 + wn * 64 + j * 8 + tig * 2;
                float v0 = acc[i][j][rr * 2 + 0];
                float v1 = acc[i][j][rr * 2 + 1];
                if (BIAS) { v0 += bias[n]; v1 += bias[n + 1]; }
                if (SPLIT) {
                    // round for downstream tf32 consumption
                    v0 = to_tf32(v0); v1 = to_tf32(v1);
                    int b_ = m >> 11, s_ = m & 2047;
                    int h_ = n >> 6,  d_ = n & 63;
                    *(float2*)&C[(((size_t)b_ * Hc + h_) * Sc + s_) * HDc + d_] =
                        make_float2(v0, v1);
                } else {
                    *(float2*)&C[(size_t)m * DOUT + n] = make_float2(v0, v1);
                }
            }
        }
    }
}

// ---------------------------------------------------------------------------
// Causal flash attention, tf32 mma. CTA = 128 queries, 4 warps,
// warp tile 32x64 (rows in-warp -> register softmax). K/V 2-stage cp.async.
// q/k/v pre-rounded to tf32 by the projection epilogue.
// ---------------------------------------------------------------------------
#define QT 128
#define KT 64
#define TS 68
#define KV_STAGE (2*KT*TS)                         // K+V, floats
#define ATTN_SMEM_FLOATS (QT*TS + 2*KV_STAGE)      // 26112 floats = 104448 B

__global__ __launch_bounds__(128, 2)
void attn_tc(const float* __restrict__ q,
             const float* __restrict__ k,
             const float* __restrict__ v,
             float* __restrict__ ctx) {
    extern __shared__ float smem[];
    float* q_s = smem;                              // [128][TS]
    const uint32_t sbase = (uint32_t)__cvta_generic_to_shared(smem);
    const uint32_t kvbase = sbase + (uint32_t)(QT * TS) * 4u;

    const int qb   = (gridDim.x - 1) - blockIdx.x;  // heavy tiles first
    const int head = blockIdx.y;
    const int b    = blockIdx.z;
    const int q0   = qb * QT;

    const float* qp    = q + ((size_t)(b * Hc + head) * Sc + q0) * HDc;
    const float* kbase = k + (size_t)(b * Hc + head) * Sc * HDc;
    const float* vbase = v + (size_t)(b * Hc + head) * Sc * HDc;

    const int tid  = threadIdx.x;
    const int warp = tid >> 5, lane = tid & 31;
    const int gid = lane >> 2, tig = lane & 3;

    // issue K/V tile jb into stage s
    auto issue_kv = [&](int jb, int s) {
        const float* kp = kbase + (size_t)jb * KT * HDc;
        const float* vp = vbase + (size_t)jb * KT * HDc;
        uint32_t kb = kvbase + (uint32_t)(s * KV_STAGE) * 4u;
        uint32_t vb = kb + (uint32_t)(KT * TS) * 4u;
        #pragma unroll
        for (int l = 0; l < 8; l++) {
            int lin = tid + l * 128;
            int r = lin >> 4, c = (lin & 15) * 4;
            cp_async16(kb + (uint32_t)(r * TS + c) * 4u, &kp[r * HDc + c]);
            cp_async16(vb + (uint32_t)(r * TS + c) * 4u, &vp[r * HDc + c]);
        }
        cp_commit();
    };

    // Load Q tile 128x64 (pre-rounded, plain float4 copies)
    #pragma unroll
    for (int l = 0; l < 16; l++) {
        int lin = tid + l * 128;
        int r = lin >> 4, c = (lin & 15) * 4;
        *(float4*)&q_s[r * TS + c] = *(const float4*)&qp[r * HDc + c];
    }

    issue_kv(0, 0);

    // softmax state: 4 row-groups per thread: (i, h) -> row warp*32+i*16+gid+h*8
    float m_st[2][2] = {{-1e30f, -1e30f}, {-1e30f, -1e30f}};
    float l_st[2][2] = {{0.0f, 0.0f}, {0.0f, 0.0f}};
    float o[2][8][4] = {};

    __syncthreads();   // q_s visible

    const int jb_end = 2 * qb + 1;
    for (int jb = 0; jb <= jb_end; jb++) {
        cp_wait<0>();
        __syncthreads();
        if (jb + 1 <= jb_end) issue_kv(jb + 1, (jb + 1) & 1);

        const float* k_s = smem + QT * TS + (jb & 1) * KV_STAGE;
        const float* v_s = k_s + KT * TS;

        // ----- S = Q @ K^T : warp tile 32x64 -----
        float s_acc[2][8][4] = {};
        #pragma unroll
        for (int kk = 0; kk < 8; kk++) {
            unsigned af[2][4];
            #pragma unroll
            for (int i = 0; i < 2; i++) {
                int rb = warp * 32 + i * 16 + gid;
                int cb = kk * 8 + tig;
                af[i][0] = __float_as_uint(q_s[rb * TS + cb]);
                af[i][1] = __float_as_uint(q_s[(rb + 8) * TS + cb]);
                af[i][2] = __float_as_uint(q_s[rb * TS + cb + 4]);
                af[i][3] = __float_as_uint(q_s[(rb + 8) * TS + cb + 4]);
            }
            #pragma unroll
            for (int j = 0; j < 8; j++) {
                unsigned bf[2];
                int key = j * 8 + gid;
                bf[0] = __float_as_uint(k_s[key * TS + kk * 8 + tig]);
                bf[1] = __float_as_uint(k_s[key * TS + kk * 8 + tig + 4]);
                #pragma unroll
                for (int i = 0; i < 2; i++)
                    mma_m16n8k8(s_acc[i][j], af[i], bf, s_acc[i][j]);
            }
        }

        // ----- scale + causal mask -----
        const bool domask = (jb >= 2 * qb);
        #pragma unroll
        for (int i = 0; i < 2; i++) {
            int row_lo = q0 + warp * 32 + i * 16 + gid;
            #pragma unroll
            for (int j = 0; j < 8; j++) {
                #pragma unroll
                for (int r = 0; r < 4; r++) {
                    float val = s_acc[i][j][r] * 0.125f;
                    if (domask) {
                        int col = jb * KT + j * 8 + tig * 2 + (r & 1);
                        int row = row_lo + ((r >= 2) ? 8 : 0);
                        if (col > row) val = -1e30f;
                    }
                    s_acc[i][j][r] = val;
                }
            }
        }

        // ----- online softmax in registers -----
        #pragma unroll
        for (int i = 0; i < 2; i++) {
            float mx_lo = -1e30f, mx_hi = -1e30f;
            #pragma unroll
            for (int j = 0; j < 8; j++) {
                mx_lo = fmaxf(mx_lo, fmaxf(s_acc[i][j][0], s_acc[i][j][1]));
                mx_hi = fmaxf(mx_hi, fmaxf(s_acc[i][j][2], s_acc[i][j][3]));
            }
            mx_lo = fmaxf(mx_lo, __shfl_xor_sync(0xFFFFFFFF, mx_lo, 1));
            mx_lo = fmaxf(mx_lo, __shfl_xor_sync(0xFFFFFFFF, mx_lo, 2));
            mx_hi = fmaxf(mx_hi, __shfl_xor_sync(0xFFFFFFFF, mx_hi, 1));
            mx_hi = fmaxf(mx_hi, __shfl_xor_sync(0xFFFFFFFF, mx_hi, 2));

            float mn_lo = fmaxf(m_st[i][0], mx_lo);
            float mn_hi = fmaxf(m_st[i][1], mx_hi);
            float sc_lo = __expf(m_st[i][0] - mn_lo);
            float sc_hi = __expf(m_st[i][1] - mn_hi);

            float sum_lo = 0.0f, sum_hi = 0.0f;
            #pragma unroll
            for (int j = 0; j < 8; j++) {
                float p0 = __expf(s_acc[i][j][0] - mn_lo);
                float p1 = __expf(s_acc[i][j][1] - mn_lo);
                float p2 = __expf(s_acc[i][j][2] - mn_hi);
                float p3 = __expf(s_acc[i][j][3] - mn_hi);
                sum_lo += p0 + p1;
                sum_hi += p2 + p3;
                s_acc[i][j][0] = to_tf32(p0);
                s_acc[i][j][1] = to_tf32(p1);
                s_acc[i][j][2] = to_tf32(p2);
                s_acc[i][j][3] = to_tf32(p3);
            }
            sum_lo += __shfl_xor_sync(0xFFFFFFFF, sum_lo, 1);
            sum_lo += __shfl_xor_sync(0xFFFFFFFF, sum_lo, 2);
            sum_hi += __shfl_xor_sync(0xFFFFFFFF, sum_hi, 1);
            sum_hi += __shfl_xor_sync(0xFFFFFFFF, sum_hi, 2);

            m_st[i][0] = mn_lo; m_st[i][1] = mn_hi;
            l_st[i][0] = l_st[i][0] * sc_lo + sum_lo;
            l_st[i][1] = l_st[i][1] * sc_hi + sum_hi;

            #pragma unroll
            for (int j = 0; j < 8; j++) {
                o[i][j][0] *= sc_lo; o[i][j][1] *= sc_lo;
                o[i][j][2] *= sc_hi; o[i][j][3] *= sc_hi;
            }
        }

        // ----- O += P @ V : P relayout via shfl -----
        const int sa = gid * 4 + (tig >> 1);
        const int sb = sa + 2;
        const bool odd = (tig & 1);
        #pragma unroll
        for (int kk = 0; kk < 8; kk++) {
            unsigned af[2][4];
            #pragma unroll
            for (int i = 0; i < 2; i++) {
                float a0e = __shfl_sync(0xFFFFFFFF, s_acc[i][kk][0], sa);
                float a0o = __shfl_sync(0xFFFFFFFF, s_acc[i][kk][1], sa);
                float a1e = __shfl_sync(0xFFFFFFFF, s_acc[i][kk][2], sa);
                float a1o = __shfl_sync(0xFFFFFFFF, s_acc[i][kk][3], sa);
                float a2e = __shfl_sync(0xFFFFFFFF, s_acc[i][kk][0], sb);
                float a2o = __shfl_sync(0xFFFFFFFF, s_acc[i][kk][1], sb);
                float a3e = __shfl_sync(0xFFFFFFFF, s_acc[i][kk][2], sb);
                float a3o = __shfl_sync(0xFFFFFFFF, s_acc[i][kk][3], sb);
                af[i][0] = __float_as_uint(odd ? a0o : a0e);
                af[i][1] = __float_as_uint(odd ? a1o : a1e);
                af[i][2] = __float_as_uint(odd ? a2o : a2e);
                af[i][3] = __float_as_uint(odd ? a3o : a3e);
            }
            #pragma unroll
            for (int j = 0; j < 8; j++) {
                unsigned bf[2];
                int d = j * 8 + gid;
                bf[0] = __float_as_uint(v_s[(kk * 8 + tig) * TS + d]);
                bf[1] = __float_as_uint(v_s[(kk * 8 + tig + 4) * TS + d]);
                #pragma unroll
                for (int i = 0; i < 2; i++)
                    mma_m16n8k8(o[i][j], af[i], bf, o[i][j]);
            }
        }
        __syncthreads();   // all warps done with this stage before overwrite
    }

    // ----- Epilogue: O /= l, round to tf32 (feeds final GEMM), store -----
    #pragma unroll
    for (int i = 0; i < 2; i++) {
        float inv_lo = 1.0f / l_st[i][0];
        float inv_hi = 1.0f / l_st[i][1];
        int grow = q0 + warp * 32 + i * 16 + gid;
        #pragma unroll
        for (int j = 0; j < 8; j++) {
            int cl = head * HDc + j * 8 + tig * 2;
            *(float2*)&ctx[((size_t)b * Sc + grow) * DOUT + cl] =
                make_float2(to_tf32(o[i][j][0] * inv_lo), to_tf32(o[i][j][1] * inv_lo));
            *(float2*)&ctx[((size_t)b * Sc + grow + 8) * DOUT + cl] =
                make_float2(to_tf32(o[i][j][2] * inv_hi), to_tf32(o[i][j][3] * inv_hi));
        }
    }
}

// ---------------------------------------------------------------------------
extern "C" void kernel_launch(void* const* d_in, const int* in_sizes, int n_in,
                              void* d_out, int out_size) {
    const float* x  = (const float*)d_in[0];
    const float* Wq = (const float*)d_in[1];
    const float* Wk = (const float*)d_in[2];
    const float* Wv = (const float*)d_in[3];
    const float* Wo = (const float*)d_in[4];
    const float* bo = (const float*)d_in[5];
    float* out = (float*)d_out;

    float *q, *k, *v, *ctx, *xr, *wr;
    cudaGetSymbolAddress((void**)&q,   g_q);
    cudaGetSymbolAddress((void**)&k,   g_k);
    cudaGetSymbolAddress((void**)&v,   g_v);
    cudaGetSymbolAddress((void**)&ctx, g_ctx);
    cudaGetSymbolAddress((void**)&xr,  g_xr);
    cudaGetSymbolAddress((void**)&wr,  g_wr);

    cudaFuncSetAttribute(gemm_tc<true,  false>,
                         cudaFuncAttributeMaxDynamicSharedMemorySize, G_SMEM_BYTES);
    cudaFuncSetAttribute(gemm_tc<false, true>,
                         cudaFuncAttributeMaxDynamicSharedMemorySize, G_SMEM_BYTES);
    const int attn_smem = ATTN_SMEM_FLOATS * sizeof(float);  // 104448
    cudaFuncSetAttribute(attn_tc,
                         cudaFuncAttributeMaxDynamicSharedMemorySize, attn_smem);

    // pre-round inputs to tf32 (so smem tiles can be raw cp.async copies)
    const int W4 = DIN * DOUT / 4;           // 262144
    round_tf32_kernel<<<(MROWS * DIN / 4 + 255) / 256, 256>>>(x, xr, MROWS * DIN / 4);
    round_tf32_kernel<<<(W4 + 255) / 256, 256>>>(Wq, wr + 0 * DIN * DOUT, W4);
    round_tf32_kernel<<<(W4 + 255) / 256, 256>>>(Wk, wr + 1 * (size_t)DIN * DOUT, W4);
    round_tf32_kernel<<<(W4 + 255) / 256, 256>>>(Wv, wr + 2 * (size_t)DIN * DOUT, W4);
    round_tf32_kernel<<<(W4 + 255) / 256, 256>>>(Wo, wr + 3 * (size_t)DIN * DOUT, W4);

    dim3 gg(DOUT / 128, MROWS / 128);   // (8, 64)

    gemm_tc<true,  false><<<gg, 128, G_SMEM_BYTES>>>(xr, wr + 0 * (size_t)DIN * DOUT, nullptr, q);
    gemm_tc<true,  false><<<gg, 128, G_SMEM_BYTES>>>(xr, wr + 1 * (size_t)DIN * DOUT, nullptr, k);
    gemm_tc<true,  false><<<gg, 128, G_SMEM_BYTES>>>(xr, wr + 2 * (size_t)DIN * DOUT, nullptr, v);

    attn_tc<<<dim3(Sc / QT, Hc, Bc), 128, attn_smem>>>(q, k, v, ctx);

    gemm_tc<false, true><<<gg, 128, G_SMEM_BYTES>>>(ctx, wr + 3 * (size_t)DIN * DOUT, bo, out);
}

// round 7
// speedup vs baseline: 4.7310x; 1.0065x over previous
#include <cuda_runtime.h>
#include <math.h>
#include <stdint.h>

#define Bc   4
#define Sc   2048
#define DIN  1024
#define DOUT 1024
#define Hc   16
#define HDc  64
#define MROWS (Bc*Sc)   // 8192

// Scratch (device globals: allocation-free per harness rules)
__device__ __align__(256) float g_q[Bc*Hc*Sc*HDc];     // phi-permuted along d
__device__ __align__(256) float g_k[Bc*Hc*Sc*HDc];     // phi-permuted along d
__device__ __align__(256) float g_v[Bc*Hc*Sc*HDc];     // psi-permuted along s
__device__ __align__(256) float g_ctx[Bc*Sc*DOUT];     // phi-permuted along DOUT
__device__ __align__(256) float g_xr[MROWS*DIN];       // tf32, phi-permuted along DIN
__device__ __align__(256) float g_wqkv[128*3072*8];    // packed [kg][3n][8]
__device__ __align__(256) float g_wo[128*1024*8];      // packed [kg][n][8]

// phi: logical k within 8-group -> physical slot (pairs (t,t+4) -> (2t,2t+1))
__host__ __device__ __forceinline__ int phi_map(int r) { return 2*(r&3) + (r>>2); }
// psi: logical seq row -> physical slot (pairs (2t,2t+1) -> (t,t+4))
__host__ __device__ __forceinline__ int psi_map(int r) { return (r>>1) + (r&1)*4; }

__device__ __forceinline__ float to_tf32(float x) {
    float r;
    asm("cvt.rna.tf32.f32 %0, %1;" : "=f"(r) : "f"(x));
    return r;
}

__device__ __forceinline__ void mma_m16n8k8(float d[4], const unsigned a[4],
                                            const unsigned b[2], const float c[4]) {
    asm volatile(
        "mma.sync.aligned.m16n8k8.row.col.f32.tf32.tf32.f32 "
        "{%0,%1,%2,%3}, {%4,%5,%6,%7}, {%8,%9}, {%10,%11,%12,%13};\n"
        : "=f"(d[0]), "=f"(d[1]), "=f"(d[2]), "=f"(d[3])
        : "r"(a[0]), "r"(a[1]), "r"(a[2]), "r"(a[3]),
          "r"(b[0]), "r"(b[1]),
          "f"(c[0]), "f"(c[1]), "f"(c[2]), "f"(c[3]));
}

__device__ __forceinline__ void cp_async16(uint32_t smem_addr, const void* gptr) {
    asm volatile("cp.async.cg.shared.global [%0], [%1], 16;\n"
                 :: "r"(smem_addr), "l"(gptr));
}
__device__ __forceinline__ void cp_commit() {
    asm volatile("cp.async.commit_group;\n");
}
template<int N>
__device__ __forceinline__ void cp_wait() {
    asm volatile("cp.async.wait_group %0;\n" :: "n"(N));
}

// ---------------------------------------------------------------------------
// Preprocess 1: x -> tf32, phi-permuted columns (groups of 8 along DIN)
// one thread per (row, 8-col group)
// ---------------------------------------------------------------------------
__global__ void permute_x_kernel(const float* __restrict__ in,
                                 float* __restrict__ out) {
    int idx = blockIdx.x * blockDim.x + threadIdx.x;   // 8192*128
    int row = idx >> 7, g = idx & 127;
    const float4* ip = (const float4*)&in[(size_t)row * DIN + g * 8];
    float4 i0 = ip[0], i1 = ip[1];
    float4* op = (float4*)&out[(size_t)row * DIN + g * 8];
    op[0] = make_float4(to_tf32(i0.x), to_tf32(i1.x), to_tf32(i0.y), to_tf32(i1.y));
    op[1] = make_float4(to_tf32(i0.z), to_tf32(i1.z), to_tf32(i0.w), to_tf32(i1.w));
}

// ---------------------------------------------------------------------------
// Preprocess 2: pack weights into fragment-ready layout [kg][n][8] with phi.
// blockIdx.y = weight index (0=Wq,1=Wk,2=Wv -> g_wqkv concat; 3=Wo -> g_wo)
// ---------------------------------------------------------------------------
__global__ void pack_w_kernel(const float* __restrict__ Wq,
                              const float* __restrict__ Wk,
                              const float* __restrict__ Wv,
                              const float* __restrict__ Wo,
                              float* __restrict__ pqkv,
                              float* __restrict__ po) {
    int idx = blockIdx.x * blockDim.x + threadIdx.x;   // 128*1024
    int w = blockIdx.y;
    int kg = idx >> 10, n = idx & 1023;
    const float* W = (w == 0) ? Wq : (w == 1) ? Wk : (w == 2) ? Wv : Wo;
    float o8[8];
    #pragma unroll
    for (int j = 0; j < 8; j++)
        o8[phi_map(j)] = to_tf32(W[(size_t)(kg * 8 + j) * DOUT + n]);
    float* dst = (w < 3) ? &pqkv[((size_t)kg * 3072 + w * 1024 + n) * 8]
                         : &po[((size_t)kg * 1024 + n) * 8];
    ((float4*)dst)[0] = make_float4(o8[0], o8[1], o8[2], o8[3]);
    ((float4*)dst)[1] = make_float4(o8[4], o8[5], o8[6], o8[7]);
}

// ---------------------------------------------------------------------------
// TF32 GEMM, cp.async 3-stage, packed-B + permuted-A (lds.64 fragments).
// CTA tile 128x128x32, 4 warps, warp tile 64x64.
// MODE 0: QKV fused (Ntot=3072) -> scatter q (phi-d), k (phi-d), v (psi-s)
// MODE 1: out-proj (Ntot=1024) -> plain + bias
// ---------------------------------------------------------------------------
#define AS_STRIDE 40
#define G_STAGE_A (128*AS_STRIDE)        // 5120 floats
#define G_STAGE_B (4*128*8)              // 4096 floats
#define G_STAGE   (G_STAGE_A + G_STAGE_B)
#define G_SMEM_BYTES (3*G_STAGE*4)       // 110592 B

template<int MODE, int NTOT>
__global__ __launch_bounds__(128, 2)
void gemm_tc(const float* __restrict__ A,
             const float* __restrict__ PW,
             const float* __restrict__ bias,
             float* __restrict__ outq,
             float* __restrict__ outk,
             float* __restrict__ outv) {
    extern __shared__ float smem[];
    const uint32_t sbase = (uint32_t)__cvta_generic_to_shared(smem);

    const int tid  = threadIdx.x;
    const int warp = tid >> 5, lane = tid & 31;
    const int wm = warp >> 1, wn = warp & 1;
    const int gid = lane >> 2, tig = lane & 3;

    const int row0 = blockIdx.y * 128;
    const int col0 = blockIdx.x * 128;

    float acc[4][8][4] = {};

    auto issue = [&](int t, int s) {
        uint32_t abase = sbase + (uint32_t)(s * G_STAGE) * 4u;
        uint32_t bbase = abase + (uint32_t)G_STAGE_A * 4u;
        #pragma unroll
        for (int l = 0; l < 8; l++) {
            int lin = tid + l * 128;
            int ar = lin >> 3, ac = (lin & 7) * 4;
            cp_async16(abase + (uint32_t)(ar * AS_STRIDE + ac) * 4u,
                       &A[(size_t)(row0 + ar) * 1024 + t * 32 + ac]);
            int kg = lin >> 8, rest = lin & 255;
            int n = rest >> 1, half = rest & 1;
            cp_async16(bbase + (uint32_t)lin * 16u,
                       &PW[((size_t)(t * 4 + kg) * NTOT + col0 + n) * 8 + half * 4]);
        }
        cp_commit();
    };

    issue(0, 0);
    issue(1, 1);

    const int NT = 1024 / 32;
    for (int t = 0; t < NT; t++) {
        cp_wait<1>();
        __syncthreads();
        if (t + 2 < NT) issue(t + 2, (t + 2) % 3);

        const float* a_s = smem + (t % 3) * G_STAGE;
        const float* b_s = a_s + G_STAGE_A;

        #pragma unroll
        for (int kk = 0; kk < 4; kk++) {
            unsigned af[4][4];
            #pragma unroll
            for (int i = 0; i < 4; i++) {
                int rb = wm * 64 + i * 16 + gid;
                float2 flo = *(const float2*)&a_s[rb * AS_STRIDE + kk * 8 + tig * 2];
                float2 fhi = *(const float2*)&a_s[(rb + 8) * AS_STRIDE + kk * 8 + tig * 2];
                af[i][0] = __float_as_uint(flo.x);
                af[i][2] = __float_as_uint(flo.y);
                af[i][1] = __float_as_uint(fhi.x);
                af[i][3] = __float_as_uint(fhi.y);
            }
            #pragma unroll
            for (int j = 0; j < 8; j++) {
                int col = wn * 64 + j * 8 + gid;
                float2 fb = *(const float2*)&b_s[(kk * 128 + col) * 8 + tig * 2];
                unsigned bf[2] = { __float_as_uint(fb.x), __float_as_uint(fb.y) };
                #pragma unroll
                for (int i = 0; i < 4; i++)
                    mma_m16n8k8(acc[i][j], af[i], bf, acc[i][j]);
            }
        }
    }

    // Epilogue
    #pragma unroll
    for (int i = 0; i < 4; i++) {
        #pragma unroll
        for (int rr = 0; rr < 2; rr++) {
            int m = row0 + wm * 64 + i * 16 + gid + rr * 8;
            #pragma unroll
            for (int j = 0; j < 8; j++) {
                int n = col0 + wn * 64 + j * 8 + tig * 2;
                float v0 = acc[i][j][rr * 2 + 0];
                float v1 = acc[i][j][rr * 2 + 1];
                if (MODE == 1) {
                    v0 += bias[n]; v1 += bias[n + 1];
                    *(float2*)&outq[(size_t)m * 1024 + n] = make_float2(v0, v1);
                } else {
                    v0 = to_tf32(v0); v1 = to_tf32(v1);
                    int which = n >> 10;
                    int nl = n & 1023;
                    int b_ = m >> 11, s_ = m & 2047;
                    int h_ = nl >> 6, d_ = nl & 63;
                    if (which == 2) {
                        // V: psi-permute seq row, d unpermuted (float2 ok)
                        int sp = (s_ & ~7) + psi_map(s_ & 7);
                        *(float2*)&outv[(((size_t)b_ * Hc + h_) * Sc + sp) * HDc + d_] =
                            make_float2(v0, v1);
                    } else {
                        // Q/K: phi-permute d (scalar stores)
                        float* dst = (which == 0) ? outq : outk;
                        int dbase = d_ & ~7;
                        int dp0 = dbase + phi_map(d_ & 7);
                        int dp1 = dbase + phi_map((d_ & 7) + 1);
                        size_t base = (((size_t)b_ * Hc + h_) * Sc + s_) * HDc;
                        dst[base + dp0] = v0;
                        dst[base + dp1] = v1;
                    }
                }
            }
        }
    }
}

// ---------------------------------------------------------------------------
// Causal flash attention, tf32 mma. CTA = 128 queries, 4 warps, warp 32x64.
// Q/K phi-permuted along d -> lds.64 fragments. V psi-permuted along seq ->
// S-accumulator registers ARE the PV A-fragments (zero shuffles).
// ---------------------------------------------------------------------------
#define QT 128
#define KT 64
#define TS 72
#define KV_STAGE (2*KT*TS)                        // 9216 floats
#define ATTN_SMEM_FLOATS (QT*TS + 2*KV_STAGE)     // 27648 floats = 110592 B

__global__ __launch_bounds__(128, 2)
void attn_tc(const float* __restrict__ q,
             const float* __restrict__ k,
             const float* __restrict__ v,
             float* __restrict__ ctx) {
    extern __shared__ float smem[];
    float* q_s = smem;                             // [128][TS]
    const uint32_t sbase = (uint32_t)__cvta_generic_to_shared(smem);
    const uint32_t kvbase = sbase + (uint32_t)(QT * TS) * 4u;

    const int qb   = (gridDim.x - 1) - blockIdx.x; // heavy tiles first
    const int head = blockIdx.y;
    const int b    = blockIdx.z;
    const int q0   = qb * QT;

    const float* qp    = q + ((size_t)(b * Hc + head) * Sc + q0) * HDc;
    const float* kbase = k + (size_t)(b * Hc + head) * Sc * HDc;
    const float* vbase = v + (size_t)(b * Hc + head) * Sc * HDc;

    const int tid  = threadIdx.x;
    const int warp = tid >> 5, lane = tid & 31;
    const int gid = lane >> 2, tig = lane & 3;

    auto issue_kv = [&](int jb, int s) {
        const float* kp = kbase + (size_t)jb * KT * HDc;
        const float* vp = vbase + (size_t)jb * KT * HDc;
        uint32_t kb = kvbase + (uint32_t)(s * KV_STAGE) * 4u;
        uint32_t vb = kb + (uint32_t)(KT * TS) * 4u;
        #pragma unroll
        for (int l = 0; l < 8; l++) {
            int lin = tid + l * 128;
            int r = lin >> 4, c = (lin & 15) * 4;
            cp_async16(kb + (uint32_t)(r * TS + c) * 4u, &kp[r * HDc + c]);
            cp_async16(vb + (uint32_t)(r * TS + c) * 4u, &vp[r * HDc + c]);
        }
    };

    // group 0: Q + KV tile 0
    #pragma unroll
    for (int l = 0; l < 16; l++) {
        int lin = tid + l * 128;
        int r = lin >> 4, c = (lin & 15) * 4;
        cp_async16(sbase + (uint32_t)(r * TS + c) * 4u, &qp[r * HDc + c]);
    }
    issue_kv(0, 0);
    cp_commit();

    float m_st[2][2] = {{-1e30f, -1e30f}, {-1e30f, -1e30f}};
    float l_st[2][2] = {{0.0f, 0.0f}, {0.0f, 0.0f}};
    float o[2][8][4] = {};

    const int jb_end = 2 * qb + 1;
    for (int jb = 0; jb <= jb_end; jb++) {
        cp_wait<0>();
        __syncthreads();
        if (jb + 1 <= jb_end) { issue_kv(jb + 1, (jb + 1) & 1); cp_commit(); }

        const float* k_s = smem + QT * TS + (jb & 1) * KV_STAGE;
        const float* v_s = k_s + KT * TS;

        // ----- S = Q @ K^T : warp tile 32x64, lds.64 fragments -----
        float s_acc[2][8][4] = {};
        #pragma unroll
        for (int kk = 0; kk < 8; kk++) {
            unsigned af[2][4];
            #pragma unroll
            for (int i = 0; i < 2; i++) {
                int rb = warp * 32 + i * 16 + gid;
                float2 flo = *(const float2*)&q_s[rb * TS + kk * 8 + tig * 2];
                float2 fhi = *(const float2*)&q_s[(rb + 8) * TS + kk * 8 + tig * 2];
                af[i][0] = __float_as_uint(flo.x);
                af[i][2] = __float_as_uint(flo.y);
                af[i][1] = __float_as_uint(fhi.x);
                af[i][3] = __float_as_uint(fhi.y);
            }
            #pragma unroll
            for (int j = 0; j < 8; j++) {
                int key = j * 8 + gid;
                float2 fb = *(const float2*)&k_s[key * TS + kk * 8 + tig * 2];
                unsigned bf[2] = { __float_as_uint(fb.x), __float_as_uint(fb.y) };
                #pragma unroll
                for (int i = 0; i < 2; i++)
                    mma_m16n8k8(s_acc[i][j], af[i], bf, s_acc[i][j]);
            }
        }

        // ----- scale + causal mask -----
        const bool domask = (jb >= 2 * qb);
        #pragma unroll
        for (int i = 0; i < 2; i++) {
            int row_lo = q0 + warp * 32 + i * 16 + gid;
            #pragma unroll
            for (int j = 0; j < 8; j++) {
                #pragma unroll
                for (int r = 0; r < 4; r++) {
                    float val = s_acc[i][j][r] * 0.125f;
                    if (domask) {
                        int col = jb * KT + j * 8 + tig * 2 + (r & 1);
                        int row = row_lo + ((r >= 2) ? 8 : 0);
                        if (col > row) val = -1e30f;
                    }
                    s_acc[i][j][r] = val;
                }
            }
        }

        // ----- online softmax in registers -----
        #pragma unroll
        for (int i = 0; i < 2; i++) {
            float mx_lo = -1e30f, mx_hi = -1e30f;
            #pragma unroll
            for (int j = 0; j < 8; j++) {
                mx_lo = fmaxf(mx_lo, fmaxf(s_acc[i][j][0], s_acc[i][j][1]));
                mx_hi = fmaxf(mx_hi, fmaxf(s_acc[i][j][2], s_acc[i][j][3]));
            }
            mx_lo = fmaxf(mx_lo, __shfl_xor_sync(0xFFFFFFFF, mx_lo, 1));
            mx_lo = fmaxf(mx_lo, __shfl_xor_sync(0xFFFFFFFF, mx_lo, 2));
            mx_hi = fmaxf(mx_hi, __shfl_xor_sync(0xFFFFFFFF, mx_hi, 1));
            mx_hi = fmaxf(mx_hi, __shfl_xor_sync(0xFFFFFFFF, mx_hi, 2));

            float mn_lo = fmaxf(m_st[i][0], mx_lo);
            float mn_hi = fmaxf(m_st[i][1], mx_hi);
            float sc_lo = __expf(m_st[i][0] - mn_lo);
            float sc_hi = __expf(m_st[i][1] - mn_hi);

            float sum_lo = 0.0f, sum_hi = 0.0f;
            #pragma unroll
            for (int j = 0; j < 8; j++) {
                float p0 = __expf(s_acc[i][j][0] - mn_lo);
                float p1 = __expf(s_acc[i][j][1] - mn_lo);
                float p2 = __expf(s_acc[i][j][2] - mn_hi);
                float p3 = __expf(s_acc[i][j][3] - mn_hi);
                sum_lo += p0 + p1;
                sum_hi += p2 + p3;
                s_acc[i][j][0] = to_tf32(p0);
                s_acc[i][j][1] = to_tf32(p1);
                s_acc[i][j][2] = to_tf32(p2);
                s_acc[i][j][3] = to_tf32(p3);
            }
            sum_lo += __shfl_xor_sync(0xFFFFFFFF, sum_lo, 1);
            sum_lo += __shfl_xor_sync(0xFFFFFFFF, sum_lo, 2);
            sum_hi += __shfl_xor_sync(0xFFFFFFFF, sum_hi, 1);
            sum_hi += __shfl_xor_sync(0xFFFFFFFF, sum_hi, 2);

            m_st[i][0] = mn_lo; m_st[i][1] = mn_hi;
            l_st[i][0] = l_st[i][0] * sc_lo + sum_lo;
            l_st[i][1] = l_st[i][1] * sc_hi + sum_hi;

            #pragma unroll
            for (int j = 0; j < 8; j++) {
                o[i][j][0] *= sc_lo; o[i][j][1] *= sc_lo;
                o[i][j][2] *= sc_hi; o[i][j][3] *= sc_hi;
            }
        }

        // ----- O += P @ V : V is psi-permuted -> s_acc regs ARE A-fragments -----
        #pragma unroll
        for (int kk = 0; kk < 8; kk++) {
            unsigned af[2][4];
            #pragma unroll
            for (int i = 0; i < 2; i++) {
                af[i][0] = __float_as_uint(s_acc[i][kk][0]);
                af[i][1] = __float_as_uint(s_acc[i][kk][2]);
                af[i][2] = __float_as_uint(s_acc[i][kk][1]);
                af[i][3] = __float_as_uint(s_acc[i][kk][3]);
            }
            #pragma unroll
            for (int j = 0; j < 8; j++) {
                int d = j * 8 + gid;
                unsigned bf[2];
                bf[0] = __float_as_uint(v_s[(kk * 8 + tig) * TS + d]);
                bf[1] = __float_as_uint(v_s[(kk * 8 + tig + 4) * TS + d]);
                #pragma unroll
                for (int i = 0; i < 2; i++)
                    mma_m16n8k8(o[i][j], af[i], bf, o[i][j]);
            }
        }
    }

    // ----- Epilogue: O /= l, tf32-round, phi-permute ctx cols (DOUT) -----
    #pragma unroll
    for (int i = 0; i < 2; i++) {
        float inv_lo = 1.0f / l_st[i][0];
        float inv_hi = 1.0f / l_st[i][1];
        int grow = q0 + warp * 32 + i * 16 + gid;
        #pragma unroll
        for (int j = 0; j < 8; j++) {
            int l0 = tig * 2;
            int clp0 = head * HDc + j * 8 + phi_map(l0);
            int clp1 = head * HDc + j * 8 + phi_map(l0 + 1);
            size_t base0 = ((size_t)b * Sc + grow) * DOUT;
            size_t base1 = ((size_t)b * Sc + grow + 8) * DOUT;
            ctx[base0 + clp0] = to_tf32(o[i][j][0] * inv_lo);
            ctx[base0 + clp1] = to_tf32(o[i][j][1] * inv_lo);
            ctx[base1 + clp0] = to_tf32(o[i][j][2] * inv_hi);
            ctx[base1 + clp1] = to_tf32(o[i][j][3] * inv_hi);
        }
    }
}

// ---------------------------------------------------------------------------
extern "C" void kernel_launch(void* const* d_in, const int* in_sizes, int n_in,
                              void* d_out, int out_size) {
    const float* x  = (const float*)d_in[0];
    const float* Wq = (const float*)d_in[1];
    const float* Wk = (const float*)d_in[2];
    const float* Wv = (const float*)d_in[3];
    const float* Wo = (const float*)d_in[4];
    const float* bo = (const float*)d_in[5];
    float* out = (float*)d_out;

    float *q, *k, *v, *ctx, *xr, *wqkv, *wo;
    cudaGetSymbolAddress((void**)&q,    g_q);
    cudaGetSymbolAddress((void**)&k,    g_k);
    cudaGetSymbolAddress((void**)&v,    g_v);
    cudaGetSymbolAddress((void**)&ctx,  g_ctx);
    cudaGetSymbolAddress((void**)&xr,   g_xr);
    cudaGetSymbolAddress((void**)&wqkv, g_wqkv);
    cudaGetSymbolAddress((void**)&wo,   g_wo);

    cudaFuncSetAttribute(gemm_tc<0, 3072>,
                         cudaFuncAttributeMaxDynamicSharedMemorySize, G_SMEM_BYTES);
    cudaFuncSetAttribute(gemm_tc<1, 1024>,
                         cudaFuncAttributeMaxDynamicSharedMemorySize, G_SMEM_BYTES);
    const int attn_smem = ATTN_SMEM_FLOATS * sizeof(float);  // 110592
    cudaFuncSetAttribute(attn_tc,
                         cudaFuncAttributeMaxDynamicSharedMemorySize, attn_smem);

    // preprocess: permute/round x; pack+round weights
    permute_x_kernel<<<MROWS * 128 / 256, 256>>>(x, xr);
    pack_w_kernel<<<dim3(128 * 1024 / 256, 4), 256>>>(Wq, Wk, Wv, Wo, wqkv, wo);

    // fused QKV projection: [8192,1024] @ [1024,3072]
    gemm_tc<0, 3072><<<dim3(24, 64), 128, G_SMEM_BYTES>>>(xr, wqkv, nullptr, q, k, v);

    attn_tc<<<dim3(Sc / QT, Hc, Bc), 128, attn_smem>>>(q, k, v, ctx);

    // output projection + bias
    gemm_tc<1, 1024><<<dim3(8, 64), 128, G_SMEM_BYTES>>>(ctx, wo, bo, out, nullptr, nullptr);
}

// round 8
// speedup vs baseline: 7.8573x; 1.6608x over previous
#include <cuda_runtime.h>
#include <cuda_fp16.h>
#include <math.h>
#include <stdint.h>

#define Bc   4
#define Sc   2048
#define DIN  1024
#define DOUT 1024
#define Hc   16
#define HDc  64
#define MROWS (Bc*Sc)   // 8192

// Scratch (device globals: allocation-free per harness rules)
__device__ __align__(256) __half g_q[Bc*Hc*Sc*HDc];      // [b,h,s,d], pre-scaled 0.125
__device__ __align__(256) __half g_k[Bc*Hc*Sc*HDc];      // [b,h,s,d]
__device__ __align__(256) __half g_v[Bc*Hc*Sc*HDc];      // [b,h,d,s] TRANSPOSED
__device__ __align__(256) __half g_ctx[Bc*Sc*DOUT];      // [b,s,n]
__device__ __align__(256) __half g_xh[MROWS*DIN];        // fp16 x
__device__ __align__(256) __half g_wqkv[3*DIN*DOUT];     // [n' (3072)][k] transposed
__device__ __align__(256) __half g_wo[DIN*DOUT];         // [n][k] transposed

// ---------------------------------------------------------------------------
// helpers
// ---------------------------------------------------------------------------
__device__ __forceinline__ void mma_fp16(float d[4], const unsigned a[4],
                                         const unsigned b[2], const float c[4]) {
    asm volatile(
        "mma.sync.aligned.m16n8k16.row.col.f32.f16.f16.f32 "
        "{%0,%1,%2,%3}, {%4,%5,%6,%7}, {%8,%9}, {%10,%11,%12,%13};\n"
        : "=f"(d[0]), "=f"(d[1]), "=f"(d[2]), "=f"(d[3])
        : "r"(a[0]), "r"(a[1]), "r"(a[2]), "r"(a[3]),
          "r"(b[0]), "r"(b[1]),
          "f"(c[0]), "f"(c[1]), "f"(c[2]), "f"(c[3]));
}

__device__ __forceinline__ void ldmatrix4(unsigned r[4], uint32_t addr) {
    asm volatile("ldmatrix.sync.aligned.m8n8.x4.shared.b16 {%0,%1,%2,%3}, [%4];"
        : "=r"(r[0]), "=r"(r[1]), "=r"(r[2]), "=r"(r[3]) : "r"(addr));
}

__device__ __forceinline__ unsigned packh2(float lo, float hi) {
    __half2 h = __floats2half2_rn(lo, hi);
    return *(unsigned*)&h;
}

__device__ __forceinline__ void cp_async16(uint32_t smem_addr, const void* gptr) {
    asm volatile("cp.async.cg.shared.global [%0], [%1], 16;\n"
                 :: "r"(smem_addr), "l"(gptr));
}
__device__ __forceinline__ void cp_commit() {
    asm volatile("cp.async.commit_group;\n");
}
template<int N>
__device__ __forceinline__ void cp_wait() {
    asm volatile("cp.async.wait_group %0;\n" :: "n"(N));
}

// ---------------------------------------------------------------------------
// Preprocess 1: x -> fp16 (8 elems per thread)
// ---------------------------------------------------------------------------
__global__ void cvt_x_kernel(const float* __restrict__ in,
                             __half* __restrict__ out, int n8) {
    int i = blockIdx.x * blockDim.x + threadIdx.x;
    if (i < n8) {
        const float4* ip = (const float4*)(in + (size_t)i * 8);
        float4 u = ip[0], w = ip[1];
        __half2 h[4] = { __floats2half2_rn(u.x, u.y), __floats2half2_rn(u.z, u.w),
                         __floats2half2_rn(w.x, w.y), __floats2half2_rn(w.z, w.w) };
        *(uint2*)(out + (size_t)i * 8)     = *(uint2*)&h[0];
        *(uint2*)(out + (size_t)i * 8 + 4) = *(uint2*)&h[2];
    }
}

// ---------------------------------------------------------------------------
// Preprocess 2: transpose-pack weights to fp16 [n][k].
// blockIdx.z: 0=Wq,1=Wk,2=Wv (-> g_wqkv rows z*1024+n), 3=Wo (-> g_wo)
// ---------------------------------------------------------------------------
__global__ void pack_wt_kernel(const float* __restrict__ Wq,
                               const float* __restrict__ Wk,
                               const float* __restrict__ Wv,
                               const float* __restrict__ Wo,
                               __half* __restrict__ wqkv,
                               __half* __restrict__ wot) {
    __shared__ float t[32][33];
    int w = blockIdx.z;
    const float* W = (w == 0) ? Wq : (w == 1) ? Wk : (w == 2) ? Wv : Wo;
    int k0 = blockIdx.y * 32, n0 = blockIdx.x * 32;
    int tx = threadIdx.x, ty = threadIdx.y;    // 32 x 8
    #pragma unroll
    for (int r = ty; r < 32; r += 8)
        t[r][tx] = W[(size_t)(k0 + r) * DOUT + n0 + tx];
    __syncthreads();
    __half* dst = (w < 3) ? wqkv + (size_t)w * DIN * DOUT : wot;
    #pragma unroll
    for (int r = ty; r < 32; r += 8)
        dst[(size_t)(n0 + r) * DIN + k0 + tx] = __float2half_rn(t[tx][r]);
}

// ---------------------------------------------------------------------------
// FP16 GEMM, cp.async 3-stage. C[8192, NTOT-chunk] = A[8192,1024] @ W^T.
// CTA 128x128x32, 256 thr (8 warps), warp tile 32x64. A via ldmatrix,
// B (stored [n][k]) via 4B LDS.
// MODE 0: fused QKV -> q (scaled 0.125), k, v (transposed [b,h,d,s]), fp16
// MODE 1: out-proj -> fp32 + bias
// ---------------------------------------------------------------------------
#define GAS 40                        // halves stride
#define GST (128*GAS)                 // 5120 halves per operand stage
#define G_STAGE_H (2*GST)             // 10240 halves
#define G_SMEM_BYTES (3*G_STAGE_H*2)  // 61440 B

template<int MODE, int NTOT>
__global__ __launch_bounds__(256, 2)
void gemm_fp16(const __half* __restrict__ A,
               const __half* __restrict__ BW,
               const float* __restrict__ bias,
               __half* __restrict__ outq,
               __half* __restrict__ outk,
               __half* __restrict__ outv,
               float* __restrict__ outf) {
    extern __shared__ __align__(16) char smem_raw[];
    __half* smem = (__half*)smem_raw;
    const uint32_t sbase = (uint32_t)__cvta_generic_to_shared(smem);

    const int tid  = threadIdx.x;
    const int warp = tid >> 5, lane = tid & 31;
    const int wm = warp >> 1, wn = warp & 1;     // 4x2 warp grid: 32m x 64n
    const int gid = lane >> 2, tig = lane & 3;

    const int row0 = blockIdx.y * 128;
    const int col0 = blockIdx.x * 128;

    float acc[2][8][4] = {};

    auto issue = [&](int t, int s) {
        uint32_t ab = sbase + (uint32_t)(s * G_STAGE_H) * 2u;
        uint32_t bb = ab + (uint32_t)GST * 2u;
        #pragma unroll
        for (int l = 0; l < 2; l++) {
            int lin = tid + l * 256;
            int r = lin >> 2, c = (lin & 3) * 8;
            cp_async16(ab + (uint32_t)(r * GAS + c) * 2u,
                       &A[(size_t)(row0 + r) * DIN + t * 32 + c]);
            cp_async16(bb + (uint32_t)(r * GAS + c) * 2u,
                       &BW[(size_t)(col0 + r) * DIN + t * 32 + c]);
        }
        cp_commit();
    };

    issue(0, 0);
    issue(1, 1);

    const int NT = DIN / 32;   // 32
    for (int t = 0; t < NT; t++) {
        cp_wait<1>();
        __syncthreads();
        if (t + 2 < NT) issue(t + 2, (t + 2) % 3);

        const __half* bs = smem + (t % 3) * G_STAGE_H + GST;
        uint32_t a_addr0 = sbase + (uint32_t)((t % 3) * G_STAGE_H) * 2u;

        #pragma unroll
        for (int kk = 0; kk < 2; kk++) {
            unsigned af[2][4];
            #pragma unroll
            for (int i = 0; i < 2; i++) {
                uint32_t a = a_addr0 +
                    (uint32_t)((wm * 32 + i * 16 + (lane & 15)) * GAS +
                               kk * 16 + (lane >> 4) * 8) * 2u;
                ldmatrix4(af[i], a);
            }
            #pragma unroll
            for (int j = 0; j < 8; j++) {
                const __half* bp = &bs[(wn * 64 + j * 8 + gid) * GAS + kk * 16 + tig * 2];
                unsigned bf[2] = { *(const unsigned*)bp, *(const unsigned*)(bp + 8) };
                #pragma unroll
                for (int i = 0; i < 2; i++)
                    mma_fp16(acc[i][j], af[i], bf, acc[i][j]);
            }
        }
    }

    // Epilogue
    #pragma unroll
    for (int i = 0; i < 2; i++) {
        #pragma unroll
        for (int rr = 0; rr < 2; rr++) {
            int m = row0 + wm * 32 + i * 16 + gid + rr * 8;
            #pragma unroll
            for (int j = 0; j < 8; j++) {
                int n = col0 + wn * 64 + j * 8 + tig * 2;
                float v0 = acc[i][j][rr * 2 + 0];
                float v1 = acc[i][j][rr * 2 + 1];
                if (MODE == 1) {
                    v0 += bias[n]; v1 += bias[n + 1];
                    *(float2*)&outf[(size_t)m * DOUT + n] = make_float2(v0, v1);
                } else {
                    int which = n >> 10;
                    int nl = n & 1023;
                    int b_ = m >> 11, s_ = m & 2047;
                    int h_ = nl >> 6, d_ = nl & 63;
                    if (which == 2) {
                        // V transposed [b,h,d,s]
                        size_t base = ((size_t)(b_ * Hc + h_) * HDc + d_) * Sc + s_;
                        outv[base]      = __float2half_rn(v0);
                        outv[base + Sc] = __float2half_rn(v1);
                    } else {
                        if (which == 0) { v0 *= 0.125f; v1 *= 0.125f; }  // fold 1/sqrt(64)
                        __half* dst = (which == 0) ? outq : outk;
                        *(__half2*)&dst[((size_t)(b_ * Hc + h_) * Sc + s_) * HDc + d_] =
                            __floats2half2_rn(v0, v1);
                    }
                }
            }
        }
    }
}

// ---------------------------------------------------------------------------
// Causal flash attention, fp16 mma. CTA = 128 queries, 8 warps, warp 16x64.
// Q pre-scaled; V pre-transposed. Register softmax; S accs feed PV directly.
// ---------------------------------------------------------------------------
#define TSH 72
#define Q_HALVES (128*TSH)          // 9216
#define KV_ST (64*TSH)              // 4608 per operand
#define KV_STAGE_H (2*KV_ST)        // 9216
#define ATTN_SMEM_BYTES ((Q_HALVES + 2*KV_STAGE_H)*2)   // 55296 B

__global__ __launch_bounds__(256, 2)
void attn_fp16(const __half* __restrict__ q,
               const __half* __restrict__ k,
               const __half* __restrict__ v,
               __half* __restrict__ ctx) {
    extern __shared__ __align__(16) char smem_raw[];
    __half* smem = (__half*)smem_raw;
    const uint32_t sbase = (uint32_t)__cvta_generic_to_shared(smem);

    const int qb   = (gridDim.x - 1) - blockIdx.x;   // heavy tiles first
    const int head = blockIdx.y;
    const int b    = blockIdx.z;
    const int q0   = qb * 128;

    const __half* qp = q + ((size_t)(b * Hc + head) * Sc + q0) * HDc;
    const __half* kb = k + (size_t)(b * Hc + head) * Sc * HDc;
    const __half* vb = v + (size_t)(b * Hc + head) * HDc * Sc;   // [d][s]

    const int tid  = threadIdx.x;
    const int warp = tid >> 5, lane = tid & 31;
    const int gid = lane >> 2, tig = lane & 3;

    auto issue_kv = [&](int jb, int s) {
        const __half* kp = kb + (size_t)jb * 64 * HDc;
        uint32_t kas = sbase + (uint32_t)(Q_HALVES + s * KV_STAGE_H) * 2u;
        uint32_t vas = kas + (uint32_t)KV_ST * 2u;
        #pragma unroll
        for (int l = 0; l < 2; l++) {
            int lin = tid + l * 256;
            int r = lin >> 3, c = (lin & 7) * 8;
            cp_async16(kas + (uint32_t)(r * TSH + c) * 2u, &kp[r * HDc + c]);
            cp_async16(vas + (uint32_t)(r * TSH + c) * 2u,
                       &vb[(size_t)r * Sc + jb * 64 + c]);
        }
    };

    // Q tile (128 x 64 halves)
    #pragma unroll
    for (int l = 0; l < 4; l++) {
        int lin = tid + l * 256;
        int r = lin >> 3, c = (lin & 7) * 8;
        cp_async16(sbase + (uint32_t)(r * TSH + c) * 2u, &qp[r * HDc + c]);
    }
    issue_kv(0, 0);
    cp_commit();

    float m0 = -1e30f, m1 = -1e30f, l0 = 0.0f, l1 = 0.0f;
    float o[8][4] = {};

    const int jb_end = 2 * qb + 1;
    for (int jb = 0; jb <= jb_end; jb++) {
        cp_wait<0>();
        __syncthreads();
        if (jb + 1 <= jb_end) { issue_kv(jb + 1, (jb + 1) & 1); cp_commit(); }

        const __half* ks = smem + Q_HALVES + (jb & 1) * KV_STAGE_H;
        const __half* vs = ks + KV_ST;

        // ----- S = Q @ K^T : warp tile 16x64 -----
        float s[8][4] = {};
        #pragma unroll
        for (int kk = 0; kk < 4; kk++) {
            unsigned af[4];
            uint32_t qa = sbase + (uint32_t)((warp * 16 + (lane & 15)) * TSH +
                                             kk * 16 + (lane >> 4) * 8) * 2u;
            ldmatrix4(af, qa);
            #pragma unroll
            for (int j = 0; j < 8; j++) {
                const __half* bp = &ks[(j * 8 + gid) * TSH + kk * 16 + tig * 2];
                unsigned bf[2] = { *(const unsigned*)bp, *(const unsigned*)(bp + 8) };
                mma_fp16(s[j], af, bf, s[j]);
            }
        }

        // ----- causal mask (scale already folded into Q) -----
        if (jb >= 2 * qb) {
            int rlo = q0 + warp * 16 + gid;
            #pragma unroll
            for (int j = 0; j < 8; j++) {
                int cbase = jb * 64 + j * 8 + tig * 2;
                if (cbase     > rlo)     s[j][0] = -1e30f;
                if (cbase + 1 > rlo)     s[j][1] = -1e30f;
                if (cbase     > rlo + 8) s[j][2] = -1e30f;
                if (cbase + 1 > rlo + 8) s[j][3] = -1e30f;
            }
        }

        // ----- online softmax in registers -----
        float mxl = -1e30f, mxh = -1e30f;
        #pragma unroll
        for (int j = 0; j < 8; j++) {
            mxl = fmaxf(mxl, fmaxf(s[j][0], s[j][1]));
            mxh = fmaxf(mxh, fmaxf(s[j][2], s[j][3]));
        }
        mxl = fmaxf(mxl, __shfl_xor_sync(0xFFFFFFFF, mxl, 1));
        mxl = fmaxf(mxl, __shfl_xor_sync(0xFFFFFFFF, mxl, 2));
        mxh = fmaxf(mxh, __shfl_xor_sync(0xFFFFFFFF, mxh, 1));
        mxh = fmaxf(mxh, __shfl_xor_sync(0xFFFFFFFF, mxh, 2));

        float mnl = fmaxf(m0, mxl), mnh = fmaxf(m1, mxh);
        float scl = __expf(m0 - mnl), sch = __expf(m1 - mnh);

        float sl = 0.0f, sh = 0.0f;
        #pragma unroll
        for (int j = 0; j < 8; j++) {
            float p0 = __expf(s[j][0] - mnl);
            float p1 = __expf(s[j][1] - mnl);
            float p2 = __expf(s[j][2] - mnh);
            float p3 = __expf(s[j][3] - mnh);
            sl += p0 + p1; sh += p2 + p3;
            s[j][0] = p0; s[j][1] = p1; s[j][2] = p2; s[j][3] = p3;
        }
        sl += __shfl_xor_sync(0xFFFFFFFF, sl, 1);
        sl += __shfl_xor_sync(0xFFFFFFFF, sl, 2);
        sh += __shfl_xor_sync(0xFFFFFFFF, sh, 1);
        sh += __shfl_xor_sync(0xFFFFFFFF, sh, 2);

        m0 = mnl; m1 = mnh;
        l0 = l0 * scl + sl;
        l1 = l1 * sch + sh;

        // pack P into fp16 A-fragments (no shuffles needed)
        unsigned pa[4][4];
        #pragma unroll
        for (int t = 0; t < 4; t++) {
            pa[t][0] = packh2(s[2*t][0],   s[2*t][1]);
            pa[t][1] = packh2(s[2*t][2],   s[2*t][3]);
            pa[t][2] = packh2(s[2*t+1][0], s[2*t+1][1]);
            pa[t][3] = packh2(s[2*t+1][2], s[2*t+1][3]);
        }

        // rescale O
        #pragma unroll
        for (int j = 0; j < 8; j++) {
            o[j][0] *= scl; o[j][1] *= scl;
            o[j][2] *= sch; o[j][3] *= sch;
        }

        // ----- O += P @ V (V transposed in smem: rows d, cols j) -----
        #pragma unroll
        for (int t = 0; t < 4; t++) {
            #pragma unroll
            for (int j = 0; j < 8; j++) {
                const __half* bp = &vs[(j * 8 + gid) * TSH + t * 16 + tig * 2];
                unsigned bf[2] = { *(const unsigned*)bp, *(const unsigned*)(bp + 8) };
                mma_fp16(o[j], pa[t], bf, o[j]);
            }
        }
    }

    // ----- Epilogue: O /= l, write ctx[b][s][head*64+d] fp16 -----
    {
        float il0 = 1.0f / l0, il1 = 1.0f / l1;
        int grow = q0 + warp * 16 + gid;
        #pragma unroll
        for (int j = 0; j < 8; j++) {
            int cl = head * HDc + j * 8 + tig * 2;
            *(__half2*)&ctx[((size_t)b * Sc + grow) * DOUT + cl] =
                __floats2half2_rn(o[j][0] * il0, o[j][1] * il0);
            *(__half2*)&ctx[((size_t)b * Sc + grow + 8) * DOUT + cl] =
                __floats2half2_rn(o[j][2] * il1, o[j][3] * il1);
        }
    }
}

// ---------------------------------------------------------------------------
extern "C" void kernel_launch(void* const* d_in, const int* in_sizes, int n_in,
                              void* d_out, int out_size) {
    const float* x  = (const float*)d_in[0];
    const float* Wq = (const float*)d_in[1];
    const float* Wk = (const float*)d_in[2];
    const float* Wv = (const float*)d_in[3];
    const float* Wo = (const float*)d_in[4];
    const float* bo = (const float*)d_in[5];
    float* out = (float*)d_out;

    __half *q, *k, *v, *ctx, *xh, *wqkv, *wo;
    cudaGetSymbolAddress((void**)&q,    g_q);
    cudaGetSymbolAddress((void**)&k,    g_k);
    cudaGetSymbolAddress((void**)&v,    g_v);
    cudaGetSymbolAddress((void**)&ctx,  g_ctx);
    cudaGetSymbolAddress((void**)&xh,   g_xh);
    cudaGetSymbolAddress((void**)&wqkv, g_wqkv);
    cudaGetSymbolAddress((void**)&wo,   g_wo);

    cudaFuncSetAttribute(gemm_fp16<0, 3072>,
                         cudaFuncAttributeMaxDynamicSharedMemorySize, G_SMEM_BYTES);
    cudaFuncSetAttribute(gemm_fp16<1, 1024>,
                         cudaFuncAttributeMaxDynamicSharedMemorySize, G_SMEM_BYTES);
    cudaFuncSetAttribute(attn_fp16,
                         cudaFuncAttributeMaxDynamicSharedMemorySize, ATTN_SMEM_BYTES);

    // preprocess
    cvt_x_kernel<<<(MROWS * DIN / 8 + 255) / 256, 256>>>(x, xh, MROWS * DIN / 8);
    pack_wt_kernel<<<dim3(32, 32, 4), dim3(32, 8)>>>(Wq, Wk, Wv, Wo, wqkv, wo);

    // fused QKV projection
    gemm_fp16<0, 3072><<<dim3(24, 64), 256, G_SMEM_BYTES>>>(
        xh, wqkv, nullptr, q, k, v, nullptr);

    attn_fp16<<<dim3(Sc / 128, Hc, Bc), 256, ATTN_SMEM_BYTES>>>(q, k, v, ctx);

    // output projection + bias (fp32 out)
    gemm_fp16<1, 1024><<<dim3(8, 64), 256, G_SMEM_BYTES>>>(
        ctx, wo, bo, nullptr, nullptr, nullptr, out);
}

// round 12
// speedup vs baseline: 8.8107x; 1.1213x over previous
#include <cuda_runtime.h>
#include <cuda_fp16.h>
#include <math.h>
#include <stdint.h>

#define Bc   4
#define Sc   2048
#define DIN  1024
#define DOUT 1024
#define Hc   16
#define HDc  64
#define MROWS (Bc*Sc)   // 8192

// Scratch (device globals: allocation-free per harness rules)
__device__ __align__(256) __half g_q[Bc*Hc*Sc*HDc];      // [b,h,s,d], pre-scaled 0.125
__device__ __align__(256) __half g_k[Bc*Hc*Sc*HDc];      // [b,h,s,d]
__device__ __align__(256) __half g_v[Bc*Hc*Sc*HDc];      // [b,h,d,s] TRANSPOSED
__device__ __align__(256) __half g_ctx[Bc*Sc*DOUT];      // [b,s,n]
__device__ __align__(256) __half g_xh[MROWS*DIN];        // fp16 x
__device__ __align__(256) __half g_wqkv[3*DIN*DOUT];     // [n' (3072)][k]
__device__ __align__(256) __half g_wo[DIN*DOUT];         // [n][k]

// ---------------------------------------------------------------------------
// helpers
// ---------------------------------------------------------------------------
__device__ __forceinline__ void mma_fp16(float d[4], const unsigned a[4],
                                         unsigned b0, unsigned b1, const float c[4]) {
    asm volatile(
        "mma.sync.aligned.m16n8k16.row.col.f32.f16.f16.f32 "
        "{%0,%1,%2,%3}, {%4,%5,%6,%7}, {%8,%9}, {%10,%11,%12,%13};\n"
        : "=f"(d[0]), "=f"(d[1]), "=f"(d[2]), "=f"(d[3])
        : "r"(a[0]), "r"(a[1]), "r"(a[2]), "r"(a[3]),
          "r"(b0), "r"(b1),
          "f"(c[0]), "f"(c[1]), "f"(c[2]), "f"(c[3]));
}

__device__ __forceinline__ void ldmatrix4(unsigned r[4], uint32_t addr) {
    asm volatile("ldmatrix.sync.aligned.m8n8.x4.shared.b16 {%0,%1,%2,%3}, [%4];"
        : "=r"(r[0]), "=r"(r[1]), "=r"(r[2]), "=r"(r[3]) : "r"(addr));
}

__device__ __forceinline__ unsigned packh2(float lo, float hi) {
    __half2 h = __floats2half2_rn(lo, hi);
    return *(unsigned*)&h;
}

__device__ __forceinline__ void cp_async16(uint32_t smem_addr, const void* gptr) {
    asm volatile("cp.async.cg.shared.global [%0], [%1], 16;\n"
                 :: "r"(smem_addr), "l"(gptr));
}
__device__ __forceinline__ void cp_commit() {
    asm volatile("cp.async.commit_group;\n");
}
template<int N>
__device__ __forceinline__ void cp_wait() {
    asm volatile("cp.async.wait_group %0;\n" :: "n"(N));
}

// ---------------------------------------------------------------------------
// Preprocess 1: x -> fp16
// ---------------------------------------------------------------------------
__global__ void cvt_x_kernel(const float* __restrict__ in,
                             __half* __restrict__ out, int n8) {
    int i = blockIdx.x * blockDim.x + threadIdx.x;
    if (i < n8) {
        const float4* ip = (const float4*)(in + (size_t)i * 8);
        float4 u = ip[0], w = ip[1];
        __half2 h[4] = { __floats2half2_rn(u.x, u.y), __floats2half2_rn(u.z, u.w),
                         __floats2half2_rn(w.x, w.y), __floats2half2_rn(w.z, w.w) };
        *(uint2*)(out + (size_t)i * 8)     = *(uint2*)&h[0];
        *(uint2*)(out + (size_t)i * 8 + 4) = *(uint2*)&h[2];
    }
}

// ---------------------------------------------------------------------------
// Preprocess 2: transpose-pack weights to fp16 [n][k]
// ---------------------------------------------------------------------------
__global__ void pack_wt_kernel(const float* __restrict__ Wq,
                               const float* __restrict__ Wk,
                               const float* __restrict__ Wv,
                               const float* __restrict__ Wo,
                               __half* __restrict__ wqkv,
                               __half* __restrict__ wot) {
    __shared__ float t[32][33];
    int w = blockIdx.z;
    const float* W = (w == 0) ? Wq : (w == 1) ? Wk : (w == 2) ? Wv : Wo;
    int k0 = blockIdx.y * 32, n0 = blockIdx.x * 32;
    int tx = threadIdx.x, ty = threadIdx.y;    // 32 x 8
    #pragma unroll
    for (int r = ty; r < 32; r += 8)
        t[r][tx] = W[(size_t)(k0 + r) * DOUT + n0 + tx];
    __syncthreads();
    __half* dst = (w < 3) ? wqkv + (size_t)w * DIN * DOUT : wot;
    #pragma unroll
    for (int r = ty; r < 32; r += 8)
        dst[(size_t)(n0 + r) * DIN + k0 + tx] = __float2half_rn(t[tx][r]);
}

// ---------------------------------------------------------------------------
// FP16 GEMM, cp.async 3-stage, ldmatrix for BOTH operands.
// CTA 128x128x32, 256 thr (8 warps), warp tile 32x64.
// MODE 0: fused QKV -> q (scaled 0.125), k, v (transposed), fp16
// MODE 1: out-proj -> fp32 + bias
// ---------------------------------------------------------------------------
#define GAS 40                        // halves stride
#define GST (128*GAS)                 // 5120 halves per operand stage
#define G_STAGE_H (2*GST)             // 10240 halves
#define G_SMEM_BYTES (3*G_STAGE_H*2)  // 61440 B

template<int MODE, int NTOT>
__global__ __launch_bounds__(256, 2)
void gemm_fp16(const __half* __restrict__ A,
               const __half* __restrict__ BW,
               const float* __restrict__ bias,
               __half* __restrict__ outq,
               __half* __restrict__ outk,
               __half* __restrict__ outv,
               float* __restrict__ outf) {
    extern __shared__ __align__(16) char smem_raw[];
    const uint32_t sbase = (uint32_t)__cvta_generic_to_shared(smem_raw);

    const int tid  = threadIdx.x;
    const int warp = tid >> 5, lane = tid & 31;
    const int wm = warp >> 1, wn = warp & 1;     // 4x2 warp grid: 32m x 64n
    const int gid = lane >> 2, tig = lane & 3;

    const int row0 = blockIdx.y * 128;
    const int col0 = blockIdx.x * 128;

    // ldmatrix lane->address components
    const int lm_row8 = lane & 7;             // row within 8x8
    const int lm_oct  = lane >> 3;            // octet 0..3
    const int lm_nhl  = (lm_oct >> 1) * 8;    // n-half select for B
    const int lm_khl  = (lm_oct & 1) * 8;     // k-half select for B

    float acc[2][8][4] = {};

    auto issue = [&](int t, int s) {
        uint32_t ab = sbase + (uint32_t)(s * G_STAGE_H) * 2u;
        uint32_t bb = ab + (uint32_t)GST * 2u;
        #pragma unroll
        for (int l = 0; l < 2; l++) {
            int lin = tid + l * 256;
            int r = lin >> 2, c = (lin & 3) * 8;
            cp_async16(ab + (uint32_t)(r * GAS + c) * 2u,
                       &A[(size_t)(row0 + r) * DIN + t * 32 + c]);
            cp_async16(bb + (uint32_t)(r * GAS + c) * 2u,
                       &BW[(size_t)(col0 + r) * DIN + t * 32 + c]);
        }
        cp_commit();
    };

    issue(0, 0);
    issue(1, 1);

    const int NT = DIN / 32;   // 32
    for (int t = 0; t < NT; t++) {
        cp_wait<1>();
        __syncthreads();
        if (t + 2 < NT) issue(t + 2, (t + 2) % 3);

        uint32_t a_addr0 = sbase + (uint32_t)((t % 3) * G_STAGE_H) * 2u;
        uint32_t b_addr0 = a_addr0 + (uint32_t)GST * 2u;

        #pragma unroll
        for (int kk = 0; kk < 2; kk++) {
            unsigned af[2][4];
            #pragma unroll
            for (int i = 0; i < 2; i++) {
                uint32_t a = a_addr0 +
                    (uint32_t)((wm * 32 + i * 16 + (lane & 15)) * GAS +
                               kk * 16 + (lane >> 4) * 8) * 2u;
                ldmatrix4(af[i], a);
            }
            #pragma unroll
            for (int jp = 0; jp < 4; jp++) {
                unsigned bm[4];
                uint32_t ba = b_addr0 +
                    (uint32_t)((wn * 64 + jp * 16 + lm_nhl + lm_row8) * GAS +
                               kk * 16 + lm_khl) * 2u;
                ldmatrix4(bm, ba);
                #pragma unroll
                for (int i = 0; i < 2; i++) {
                    mma_fp16(acc[i][2*jp],     af[i], bm[0], bm[1], acc[i][2*jp]);
                    mma_fp16(acc[i][2*jp + 1], af[i], bm[2], bm[3], acc[i][2*jp + 1]);
                }
            }
        }
    }

    // Epilogue
    #pragma unroll
    for (int i = 0; i < 2; i++) {
        #pragma unroll
        for (int rr = 0; rr < 2; rr++) {
            int m = row0 + wm * 32 + i * 16 + gid + rr * 8;
            #pragma unroll
            for (int j = 0; j < 8; j++) {
                int n = col0 + wn * 64 + j * 8 + tig * 2;
                float v0 = acc[i][j][rr * 2 + 0];
                float v1 = acc[i][j][rr * 2 + 1];
                if (MODE == 1) {
                    v0 += bias[n]; v1 += bias[n + 1];
                    *(float2*)&outf[(size_t)m * DOUT + n] = make_float2(v0, v1);
                } else {
                    int which = n >> 10;
                    int nl = n & 1023;
                    int b_ = m >> 11, s_ = m & 2047;
                    int h_ = nl >> 6, d_ = nl & 63;
                    if (which == 2) {
                        // V transposed [b,h,d,s]
                        size_t base = ((size_t)(b_ * Hc + h_) * HDc + d_) * Sc + s_;
                        outv[base]      = __float2half_rn(v0);
                        outv[base + Sc] = __float2half_rn(v1);
                    } else {
                        if (which == 0) { v0 *= 0.125f; v1 *= 0.125f; }  // fold 1/sqrt(64)
                        __half* dst = (which == 0) ? outq : outk;
                        *(__half2*)&dst[((size_t)(b_ * Hc + h_) * Sc + s_) * HDc + d_] =
                            __floats2half2_rn(v0, v1);
                    }
                }
            }
        }
    }
}

// ---------------------------------------------------------------------------
// Causal flash attention, fp16 mma, ldmatrix K/V fragments.
// CTA = 128 queries, 8 warps, warp 16x64. Q pre-scaled; V pre-transposed.
// ---------------------------------------------------------------------------
#define TSH 72
#define Q_HALVES (128*TSH)
#define KV_ST (64*TSH)
#define KV_STAGE_H (2*KV_ST)
#define ATTN_SMEM_BYTES ((Q_HALVES + 2*KV_STAGE_H)*2)   // 55296 B

__global__ __launch_bounds__(256, 2)
void attn_fp16(const __half* __restrict__ q,
               const __half* __restrict__ k,
               const __half* __restrict__ v,
               __half* __restrict__ ctx) {
    extern __shared__ __align__(16) char smem_raw[];
    const uint32_t sbase = (uint32_t)__cvta_generic_to_shared(smem_raw);

    const int qb   = (gridDim.x - 1) - blockIdx.x;   // heavy tiles first
    const int head = blockIdx.y;
    const int b    = blockIdx.z;
    const int q0   = qb * 128;

    const __half* qp = q + ((size_t)(b * Hc + head) * Sc + q0) * HDc;
    const __half* kb = k + (size_t)(b * Hc + head) * Sc * HDc;
    const __half* vb = v + (size_t)(b * Hc + head) * HDc * Sc;   // [d][s]

    const int tid  = threadIdx.x;
    const int warp = tid >> 5, lane = tid & 31;
    const int gid = lane >> 2, tig = lane & 3;

    const int lm_row8 = lane & 7;
    const int lm_oct  = lane >> 3;
    const int lm_nhl  = (lm_oct >> 1) * 8;
    const int lm_khl  = (lm_oct & 1) * 8;

    auto issue_kv = [&](int jb, int s) {
        const __half* kp = kb + (size_t)jb * 64 * HDc;
        uint32_t kas = sbase + (uint32_t)(Q_HALVES + s * KV_STAGE_H) * 2u;
        uint32_t vas = kas + (uint32_t)KV_ST * 2u;
        #pragma unroll
        for (int l = 0; l < 2; l++) {
            int lin = tid + l * 256;
            int r = lin >> 3, c = (lin & 7) * 8;
            cp_async16(kas + (uint32_t)(r * TSH + c) * 2u, &kp[r * HDc + c]);
            cp_async16(vas + (uint32_t)(r * TSH + c) * 2u,
                       &vb[(size_t)r * Sc + jb * 64 + c]);
        }
    };

    // Q tile
    #pragma unroll
    for (int l = 0; l < 4; l++) {
        int lin = tid + l * 256;
        int r = lin >> 3, c = (lin & 7) * 8;
        cp_async16(sbase + (uint32_t)(r * TSH + c) * 2u, &qp[r * HDc + c]);
    }
    issue_kv(0, 0);
    cp_commit();

    float m0 = -1e30f, m1 = -1e30f, l0 = 0.0f, l1 = 0.0f;
    float o[8][4] = {};

    const int jb_end = 2 * qb + 1;
    for (int jb = 0; jb <= jb_end; jb++) {
        cp_wait<0>();
        __syncthreads();
        if (jb + 1 <= jb_end) { issue_kv(jb + 1, (jb + 1) & 1); cp_commit(); }

        uint32_t ks_a = sbase + (uint32_t)(Q_HALVES + (jb & 1) * KV_STAGE_H) * 2u;
        uint32_t vs_a = ks_a + (uint32_t)KV_ST * 2u;

        // ----- S = Q @ K^T : warp tile 16x64 -----
        float s[8][4] = {};
        #pragma unroll
        for (int kk = 0; kk < 4; kk++) {
            unsigned af[4];
            uint32_t qa = sbase + (uint32_t)((warp * 16 + (lane & 15)) * TSH +
                                             kk * 16 + (lane >> 4) * 8) * 2u;
            ldmatrix4(af, qa);
            #pragma unroll
            for (int jp = 0; jp < 4; jp++) {
                unsigned bm[4];
                uint32_t ba = ks_a + (uint32_t)((jp * 16 + lm_nhl + lm_row8) * TSH +
                                                kk * 16 + lm_khl) * 2u;
                ldmatrix4(bm, ba);
                mma_fp16(s[2*jp],     af, bm[0], bm[1], s[2*jp]);
                mma_fp16(s[2*jp + 1], af, bm[2], bm[3], s[2*jp + 1]);
            }
        }

        // ----- causal mask (scale folded into Q) -----
        if (jb >= 2 * qb) {
            int rlo = q0 + warp * 16 + gid;
            #pragma unroll
            for (int j = 0; j < 8; j++) {
                int cbase = jb * 64 + j * 8 + tig * 2;
                if (cbase     > rlo)     s[j][0] = -1e30f;
                if (cbase + 1 > rlo)     s[j][1] = -1e30f;
                if (cbase     > rlo + 8) s[j][2] = -1e30f;
                if (cbase + 1 > rlo + 8) s[j][3] = -1e30f;
            }
        }

        // ----- online softmax in registers -----
        float mxl = -1e30f, mxh = -1e30f;
        #pragma unroll
        for (int j = 0; j < 8; j++) {
            mxl = fmaxf(mxl, fmaxf(s[j][0], s[j][1]));
            mxh = fmaxf(mxh, fmaxf(s[j][2], s[j][3]));
        }
        mxl = fmaxf(mxl, __shfl_xor_sync(0xFFFFFFFF, mxl, 1));
        mxl = fmaxf(mxl, __shfl_xor_sync(0xFFFFFFFF, mxl, 2));
        mxh = fmaxf(mxh, __shfl_xor_sync(0xFFFFFFFF, mxh, 1));
        mxh = fmaxf(mxh, __shfl_xor_sync(0xFFFFFFFF, mxh, 2));

        float mnl = fmaxf(m0, mxl), mnh = fmaxf(m1, mxh);
        float scl = __expf(m0 - mnl), sch = __expf(m1 - mnh);

        float sl = 0.0f, sh = 0.0f;
        #pragma unroll
        for (int j = 0; j < 8; j++) {
            float p0 = __expf(s[j][0] - mnl);
            float p1 = __expf(s[j][1] - mnl);
            float p2 = __expf(s[j][2] - mnh);
            float p3 = __expf(s[j][3] - mnh);
            sl += p0 + p1; sh += p2 + p3;
            s[j][0] = p0; s[j][1] = p1; s[j][2] = p2; s[j][3] = p3;
        }
        sl += __shfl_xor_sync(0xFFFFFFFF, sl, 1);
        sl += __shfl_xor_sync(0xFFFFFFFF, sl, 2);
        sh += __shfl_xor_sync(0xFFFFFFFF, sh, 1);
        sh += __shfl_xor_sync(0xFFFFFFFF, sh, 2);

        m0 = mnl; m1 = mnh;
        l0 = l0 * scl + sl;
        l1 = l1 * sch + sh;

        // pack P into fp16 A-fragments (no shuffles)
        unsigned pa[4][4];
        #pragma unroll
        for (int t = 0; t < 4; t++) {
            pa[t][0] = packh2(s[2*t][0],   s[2*t][1]);
            pa[t][1] = packh2(s[2*t][2],   s[2*t][3]);
            pa[t][2] = packh2(s[2*t+1][0], s[2*t+1][1]);
            pa[t][3] = packh2(s[2*t+1][2], s[2*t+1][3]);
        }

        // rescale O
        #pragma unroll
        for (int j = 0; j < 8; j++) {
            o[j][0] *= scl; o[j][1] *= scl;
            o[j][2] *= sch; o[j][3] *= sch;
        }

        // ----- O += P @ V (V rows = d, cols = s) -----
        #pragma unroll
        for (int t = 0; t < 4; t++) {
            #pragma unroll
            for (int jp = 0; jp < 4; jp++) {
                unsigned bm[4];
                uint32_t ba = vs_a + (uint32_t)((jp * 16 + lm_nhl + lm_row8) * TSH +
                                                t * 16 + lm_khl) * 2u;
                ldmatrix4(bm, ba);
                mma_fp16(o[2*jp],     pa[t], bm[0], bm[1], o[2*jp]);
                mma_fp16(o[2*jp + 1], pa[t], bm[2], bm[3], o[2*jp + 1]);
            }
        }
    }

    // ----- Epilogue -----
    {
        float il0 = 1.0f / l0, il1 = 1.0f / l1;
        int grow = q0 + warp * 16 + gid;
        #pragma unroll
        for (int j = 0; j < 8; j++) {
            int cl = head * HDc + j * 8 + tig * 2;
            *(__half2*)&g_ctx[((size_t)b * Sc + grow) * DOUT + cl] =
                __floats2half2_rn(o[j][0] * il0, o[j][1] * il0);
            *(__half2*)&g_ctx[((size_t)b * Sc + grow + 8) * DOUT + cl] =
                __floats2half2_rn(o[j][2] * il1, o[j][3] * il1);
        }
    }
    (void)ctx;
}

// ---------------------------------------------------------------------------
extern "C" void kernel_launch(void* const* d_in, const int* in_sizes, int n_in,
                              void* d_out, int out_size) {
    const float* x  = (const float*)d_in[0];
    const float* Wq = (const float*)d_in[1];
    const float* Wk = (const float*)d_in[2];
    const float* Wv = (const float*)d_in[3];
    const float* Wo = (const float*)d_in[4];
    const float* bo = (const float*)d_in[5];
    float* out = (float*)d_out;

    __half *q, *k, *v, *ctx, *xh, *wqkv, *wo;
    cudaGetSymbolAddress((void**)&q,    g_q);
    cudaGetSymbolAddress((void**)&k,    g_k);
    cudaGetSymbolAddress((void**)&v,    g_v);
    cudaGetSymbolAddress((void**)&ctx,  g_ctx);
    cudaGetSymbolAddress((void**)&xh,   g_xh);
    cudaGetSymbolAddress((void**)&wqkv, g_wqkv);
    cudaGetSymbolAddress((void**)&wo,   g_wo);

    cudaFuncSetAttribute(gemm_fp16<0, 3072>,
                         cudaFuncAttributeMaxDynamicSharedMemorySize, G_SMEM_BYTES);
    cudaFuncSetAttribute(gemm_fp16<1, 1024>,
                         cudaFuncAttributeMaxDynamicSharedMemorySize, G_SMEM_BYTES);
    cudaFuncSetAttribute(attn_fp16,
                         cudaFuncAttributeMaxDynamicSharedMemorySize, ATTN_SMEM_BYTES);

    // preprocess
    cvt_x_kernel<<<(MROWS * DIN / 8 + 255) / 256, 256>>>(x, xh, MROWS * DIN / 8);
    pack_wt_kernel<<<dim3(32, 32, 4), dim3(32, 8)>>>(Wq, Wk, Wv, Wo, wqkv, wo);

    // fused QKV projection
    gemm_fp16<0, 3072><<<dim3(24, 64), 256, G_SMEM_BYTES>>>(
        xh, wqkv, nullptr, q, k, v, nullptr);

    attn_fp16<<<dim3(Sc / 128, Hc, Bc), 256, ATTN_SMEM_BYTES>>>(q, k, v, ctx);

    // output projection + bias (fp32 out)
    gemm_fp16<1, 1024><<<dim3(8, 64), 256, G_SMEM_BYTES>>>(
        ctx, wo, bo, nullptr, nullptr, nullptr, out);
}